// round 11
// baseline (speedup 1.0000x reference)
#include <cuda_runtime.h>
#include <cuda_bf16.h>
#include <cuda_fp16.h>
#include <math.h>
#include <stdint.h>

#define NB   4
#define LEN  5440
#define MTOT (NB*LEN)      // 21760
#define DM   256
#define NH   8
#define NG   128

// ===========================================================================
// Scratch (allocation-free __device__ globals)
// ===========================================================================
__device__ uint4 g_qh[MTOT*32];                      // query bf16 hi (row-major)
__device__ uint4 g_ifh[MTOT*32], g_ifl[MTOT*32];     // input_flatten split
__device__ uint4 g_mh[MTOT*32],  g_ml[MTOT*32];      // mix (sample output) split
__device__ uint4 g_wembh[4096*32];                   // offset-embed W bf16 hi
__device__ uint4 g_vwh[256*32],   g_vwl[256*32];     // value W split
__device__ uint4 g_owh[256*32],   g_owl[256*32];     // out W split
__device__ __half g_value[MTOT*DM];                  // value projection (fp16)
__device__ float g_offaw[(size_t)NG*MTOT*3];         // [group][row][3]

// ===========================================================================
__device__ __forceinline__ uint32_t s2u(const void* p) {
  uint32_t a;
  asm("{ .reg .u64 t; cvta.to.shared.u64 t, %1; cvt.u32.u64 %0, t; }" : "=r"(a) : "l"(p));
  return a;
}
__device__ __forceinline__ void ldsm4(uint32_t& r0, uint32_t& r1, uint32_t& r2,
                                      uint32_t& r3, uint32_t addr) {
  asm volatile("ldmatrix.sync.aligned.m8n8.x4.shared.b16 {%0,%1,%2,%3}, [%4];"
               : "=r"(r0), "=r"(r1), "=r"(r2), "=r"(r3) : "r"(addr));
}
__device__ __forceinline__ void mma16816(float& c0, float& c1, float& c2, float& c3,
                                         uint32_t a0, uint32_t a1, uint32_t a2, uint32_t a3,
                                         uint32_t b0, uint32_t b1) {
  asm volatile("mma.sync.aligned.m16n8k16.row.col.f32.bf16.bf16.f32 "
               "{%0,%1,%2,%3}, {%4,%5,%6,%7}, {%8,%9}, {%0,%1,%2,%3};"
               : "+f"(c0), "+f"(c1), "+f"(c2), "+f"(c3)
               : "r"(a0), "r"(a1), "r"(a2), "r"(a3), "r"(b0), "r"(b1));
}
#define CP_ASYNC16(dst, src) \
  asm volatile("cp.async.cg.shared.global [%0], [%1], 16;" :: "r"(dst), "l"(src))
#define CP_COMMIT() asm volatile("cp.async.commit_group;")
#define CP_WAIT(n)  asm volatile("cp.async.wait_group %0;" :: "n"(n) : "memory")

// ===========================================================================
// prep kernels
// ===========================================================================
__device__ __forceinline__ void split_body(const float4* __restrict__ in,
                                           __nv_bfloat162* __restrict__ hi,
                                           __nv_bfloat162* __restrict__ lo, int i) {
  float4 v = in[i];
  __nv_bfloat16 hx = __float2bfloat16_rn(v.x);
  __nv_bfloat16 hy = __float2bfloat16_rn(v.y);
  __nv_bfloat16 hz = __float2bfloat16_rn(v.z);
  __nv_bfloat16 hw = __float2bfloat16_rn(v.w);
  hi[2*i+0] = __nv_bfloat162(hx, hy);
  hi[2*i+1] = __nv_bfloat162(hz, hw);
  lo[2*i+0] = __nv_bfloat162(__float2bfloat16_rn(v.x - __bfloat162float(hx)),
                             __float2bfloat16_rn(v.y - __bfloat162float(hy)));
  lo[2*i+1] = __nv_bfloat162(__float2bfloat16_rn(v.z - __bfloat162float(hz)),
                             __float2bfloat16_rn(v.w - __bfloat162float(hw)));
}

__global__ void __launch_bounds__(256)
split_hi(const float4* __restrict__ in, __nv_bfloat162* __restrict__ hi, int n4) {
  int i = blockIdx.x*256 + threadIdx.x;
  if (i >= n4) return;
  float4 v = in[i];
  hi[2*i+0] = __nv_bfloat162(__float2bfloat16_rn(v.x), __float2bfloat16_rn(v.y));
  hi[2*i+1] = __nv_bfloat162(__float2bfloat16_rn(v.z), __float2bfloat16_rn(v.w));
}

// fused split: input_flatten (0..5439) + valW (5440..5503) + outW (5504..5567)
__global__ void __launch_bounds__(256)
split_ifw(const float4* __restrict__ inf, __nv_bfloat162* __restrict__ ifh,
          __nv_bfloat162* __restrict__ ifl,
          const float4* __restrict__ w1, __nv_bfloat162* __restrict__ h1,
          __nv_bfloat162* __restrict__ l1,
          const float4* __restrict__ w2, __nv_bfloat162* __restrict__ h2,
          __nv_bfloat162* __restrict__ l2) {
  int b = blockIdx.x;
  if (b < 5440)      split_body(inf, ifh, ifl, b*256 + threadIdx.x);
  else if (b < 5504) split_body(w1, h1, l1, (b-5440)*256 + threadIdx.x);
  else               split_body(w2, h2, l2, (b-5504)*256 + threadIdx.x);
}

// ===========================================================================
// 3-term split-bf16 GEMM body (value / out projections — precision path).
// 512 threads, 16 warps (4M x 4N), 32x32 warp tile. A hi|lo resident.
// MODE 0: bias + fp32 store.  MODE 2: bias + fp16 store.
// ===========================================================================
template<int MODE, int NT>
__device__ __forceinline__ void gemm_body(
    const uint4* __restrict__ Ah, const uint4* __restrict__ Al,
    const uint4* __restrict__ Bh, const uint4* __restrict__ Bl,
    const float* __restrict__ c0,
    void* __restrict__ OutV, int r0, int N0) {
  extern __shared__ char dsm[];
  const uint32_t as = s2u(dsm);            // A: 128 rows x 1024B = 131072
  const uint32_t bsb = as + 131072u;       // B: 3 x 32768 (hi 16KB | lo 16KB)
  const int tid = threadIdx.x;
  const int wid = tid >> 5, lane = tid & 31;
  const int mw = wid & 3, nw = wid >> 2;

#pragma unroll
  for (int it = 0; it < 16; ++it) {
    int i = it*512 + tid;
    int r = i >> 6, u = i & 63;
    int half = u >> 5, uu = u & 31;
    int s = (half << 2) + (uu >> 3), c = uu & 7;
    const uint4* src = (half ? Al : Ah) + (size_t)(r0 + r)*32 + uu;
    uint32_t dst = as + (uint32_t)r*1024u + (uint32_t)s*128u + (uint32_t)((c ^ (r & 7))*16);
    CP_ASYNC16(dst, src);
  }
  CP_COMMIT();

  const int lA = mw*32 + (lane & 15);
  const int jj = lane >> 4;
  const int nB = nw*32 + (lane & 15);
  const uint32_t pA = as + (uint32_t)lA*1024u;
  const int swA = lA & 7, swB = nB & 7;

  for (int nt = 0; nt < NT; ++nt) {
    float acc[2][4][4];
#pragma unroll
    for (int a = 0; a < 2; ++a)
#pragma unroll
      for (int b = 0; b < 4; ++b)
#pragma unroll
        for (int d = 0; d < 4; ++d) acc[a][b][d] = 0.f;

    const int nrow0 = N0 + nt*128;

    auto prefetchC4 = [&](int c4, int bi) {
#pragma unroll
      for (int it = 0; it < 4; ++it) {
        int i = it*512 + tid;
        int n = i >> 4, u = i & 15;
        int sub = u >> 3, c = u & 7;
        const uint4* src = (sub ? Bl : Bh) + (size_t)(nrow0 + n)*32 + c4*8 + c;
        uint32_t dst = bsb + (uint32_t)bi*32768u + (uint32_t)sub*16384u
                     + (uint32_t)n*128u + (uint32_t)((c ^ (n & 7))*16);
        CP_ASYNC16(dst, src);
      }
      CP_COMMIT();
    };

    prefetchC4(0, 0);
    prefetchC4(1, 1);

#pragma unroll
    for (int c4 = 0; c4 < 4; ++c4) {
      if (c4 == 3) { CP_WAIT(0); } else { CP_WAIT(1); }
      __syncthreads();
      if (c4 + 2 < 4) prefetchC4(c4 + 2, (c4 + 2) % 3);

      const uint32_t bs  = bsb + (uint32_t)(c4 % 3)*32768u;
      const uint32_t aBh = pA + (uint32_t)c4*128u;
      const uint32_t aBl = pA + (uint32_t)(4 + c4)*128u;
#pragma unroll
      for (int ks = 0; ks < 4; ++ks) {
        const int cc = ks*2 + jj;
        const uint32_t csw = (uint32_t)((cc ^ swA)*16);
        uint32_t ah[2][4], al[2][4];
        ldsm4(ah[0][0], ah[0][1], ah[0][2], ah[0][3], aBh + csw);
        ldsm4(ah[1][0], ah[1][1], ah[1][2], ah[1][3], aBh + 16384u + csw);
        ldsm4(al[0][0], al[0][1], al[0][2], al[0][3], aBl + csw);
        ldsm4(al[1][0], al[1][1], al[1][2], al[1][3], aBl + 16384u + csw);
        const uint32_t bsw = (uint32_t)((cc ^ swB)*16);
        uint32_t bh[2][4], bl[2][4];
#pragma unroll
        for (int qt = 0; qt < 2; ++qt) {
          ldsm4(bh[qt][0], bh[qt][1], bh[qt][2], bh[qt][3],
                bs + (uint32_t)nB*128u + (uint32_t)qt*2048u + bsw);
          ldsm4(bl[qt][0], bl[qt][1], bl[qt][2], bl[qt][3],
                bs + 16384u + (uint32_t)nB*128u + (uint32_t)qt*2048u + bsw);
        }
#pragma unroll
        for (int qt = 0; qt < 2; ++qt)
#pragma unroll
          for (int mt = 0; mt < 2; ++mt) {
            mma16816(acc[mt][qt*2  ][0], acc[mt][qt*2  ][1], acc[mt][qt*2  ][2], acc[mt][qt*2  ][3],
                     ah[mt][0], ah[mt][1], ah[mt][2], ah[mt][3], bh[qt][0], bh[qt][2]);
            mma16816(acc[mt][qt*2+1][0], acc[mt][qt*2+1][1], acc[mt][qt*2+1][2], acc[mt][qt*2+1][3],
                     ah[mt][0], ah[mt][1], ah[mt][2], ah[mt][3], bh[qt][1], bh[qt][3]);
          }
#pragma unroll
        for (int qt = 0; qt < 2; ++qt)
#pragma unroll
          for (int mt = 0; mt < 2; ++mt) {
            mma16816(acc[mt][qt*2  ][0], acc[mt][qt*2  ][1], acc[mt][qt*2  ][2], acc[mt][qt*2  ][3],
                     al[mt][0], al[mt][1], al[mt][2], al[mt][3], bh[qt][0], bh[qt][2]);
            mma16816(acc[mt][qt*2+1][0], acc[mt][qt*2+1][1], acc[mt][qt*2+1][2], acc[mt][qt*2+1][3],
                     al[mt][0], al[mt][1], al[mt][2], al[mt][3], bh[qt][1], bh[qt][3]);
          }
#pragma unroll
        for (int qt = 0; qt < 2; ++qt)
#pragma unroll
          for (int mt = 0; mt < 2; ++mt) {
            mma16816(acc[mt][qt*2  ][0], acc[mt][qt*2  ][1], acc[mt][qt*2  ][2], acc[mt][qt*2  ][3],
                     ah[mt][0], ah[mt][1], ah[mt][2], ah[mt][3], bl[qt][0], bl[qt][2]);
            mma16816(acc[mt][qt*2+1][0], acc[mt][qt*2+1][1], acc[mt][qt*2+1][2], acc[mt][qt*2+1][3],
                     ah[mt][0], ah[mt][1], ah[mt][2], ah[mt][3], bl[qt][1], bl[qt][3]);
          }
      }
    }
    __syncthreads();

#pragma unroll
    for (int mt = 0; mt < 2; ++mt)
#pragma unroll
      for (int h = 0; h < 2; ++h) {
        int row = r0 + mw*32 + mt*16 + (lane >> 2) + h*8;
#pragma unroll
        for (int j = 0; j < 4; ++j) {
          int col = nt*128 + nw*32 + j*8 + (lane & 3)*2;
          float ox = acc[mt][j][h*2+0] + c0[col];
          float oy = acc[mt][j][h*2+1] + c0[col+1];
          if (MODE == 0) {
            float2 o; o.x = ox; o.y = oy;
            *reinterpret_cast<float2*>((float*)OutV + (size_t)row*256 + col) = o;
          } else {
            __half2 o = __floats2half2_rn(ox, oy);
            *reinterpret_cast<__half2*>((__half*)OutV + (size_t)row*256 + col) = o;
          }
        }
      }
  }
}

// ===========================================================================
// Single-pass bf16 GEMM body (offset path — error-tolerant; see analysis).
// A hi-only resident (64KB); B hi-only 3 x 16KB chunks. NT=2.
// Epilogue: silu + group dot -> g_offaw.
// ===========================================================================
__device__ __forceinline__ void gemm1_body(
    const uint4* __restrict__ Ah, const uint4* __restrict__ Bh,
    const float* __restrict__ sow, const float* __restrict__ attw,
    float* __restrict__ Out, int r0, int N0) {
  extern __shared__ char dsm[];
  const uint32_t as = s2u(dsm);            // A: 128 rows x 512B = 65536
  const uint32_t bsb = as + 65536u;        // B: 3 x 16384
  const int tid = threadIdx.x;
  const int wid = tid >> 5, lane = tid & 31;
  const int mw = wid & 3, nw = wid >> 2;

  // A hi load: 4096 uint4, swizzled, row stride 512B (4 segs of 128B)
#pragma unroll
  for (int it = 0; it < 8; ++it) {
    int i = it*512 + tid;
    int r = i >> 5, uu = i & 31;
    int s = uu >> 3, c = uu & 7;
    const uint4* src = Ah + (size_t)(r0 + r)*32 + uu;
    uint32_t dst = as + (uint32_t)r*512u + (uint32_t)s*128u + (uint32_t)((c ^ (r & 7))*16);
    CP_ASYNC16(dst, src);
  }
  CP_COMMIT();

  const int lA = mw*32 + (lane & 15);
  const int jj = lane >> 4;
  const int nB = nw*32 + (lane & 15);
  const uint32_t pA = as + (uint32_t)lA*512u;
  const int swA = lA & 7, swB = nB & 7;

  for (int nt = 0; nt < 2; ++nt) {
    float acc[2][4][4];
#pragma unroll
    for (int a = 0; a < 2; ++a)
#pragma unroll
      for (int b = 0; b < 4; ++b)
#pragma unroll
        for (int d = 0; d < 4; ++d) acc[a][b][d] = 0.f;

    const int nrow0 = N0 + nt*128;

    auto prefetchC4 = [&](int c4, int bi) {
#pragma unroll
      for (int it = 0; it < 2; ++it) {
        int i = it*512 + tid;              // 0..1023
        int n = i >> 3, c = i & 7;
        const uint4* src = Bh + (size_t)(nrow0 + n)*32 + c4*8 + c;
        uint32_t dst = bsb + (uint32_t)bi*16384u
                     + (uint32_t)n*128u + (uint32_t)((c ^ (n & 7))*16);
        CP_ASYNC16(dst, src);
      }
      CP_COMMIT();
    };

    prefetchC4(0, 0);
    prefetchC4(1, 1);

#pragma unroll
    for (int c4 = 0; c4 < 4; ++c4) {
      if (c4 == 3) { CP_WAIT(0); } else { CP_WAIT(1); }
      __syncthreads();
      if (c4 + 2 < 4) prefetchC4(c4 + 2, (c4 + 2) % 3);

      const uint32_t bs = bsb + (uint32_t)(c4 % 3)*16384u;
      const uint32_t aB = pA + (uint32_t)c4*128u;
#pragma unroll
      for (int ks = 0; ks < 4; ++ks) {
        const int cc = ks*2 + jj;
        const uint32_t csw = (uint32_t)((cc ^ swA)*16);
        uint32_t ah[2][4];
        ldsm4(ah[0][0], ah[0][1], ah[0][2], ah[0][3], aB + csw);
        ldsm4(ah[1][0], ah[1][1], ah[1][2], ah[1][3], aB + 8192u + csw);
        const uint32_t bsw = (uint32_t)((cc ^ swB)*16);
        uint32_t bh[2][4];
#pragma unroll
        for (int qt = 0; qt < 2; ++qt)
          ldsm4(bh[qt][0], bh[qt][1], bh[qt][2], bh[qt][3],
                bs + (uint32_t)nB*128u + (uint32_t)qt*2048u + bsw);
#pragma unroll
        for (int qt = 0; qt < 2; ++qt)
#pragma unroll
          for (int mt = 0; mt < 2; ++mt) {
            mma16816(acc[mt][qt*2  ][0], acc[mt][qt*2  ][1], acc[mt][qt*2  ][2], acc[mt][qt*2  ][3],
                     ah[mt][0], ah[mt][1], ah[mt][2], ah[mt][3], bh[qt][0], bh[qt][2]);
            mma16816(acc[mt][qt*2+1][0], acc[mt][qt*2+1][1], acc[mt][qt*2+1][2], acc[mt][qt*2+1][3],
                     ah[mt][0], ah[mt][1], ah[mt][2], ah[mt][3], bh[qt][1], bh[qt][3]);
          }
      }
    }
    __syncthreads();

    // epilogue: silu + group-of-32 dot
    const float2* sw2 = reinterpret_cast<const float2*>(sow);
    int g = (N0 + nt*128 + nw*32) >> 5;
    float wx[4][2], wy[4][2], wl[4][2];
#pragma unroll
    for (int j = 0; j < 4; ++j) {
      int col = g*32 + j*8 + (lane & 3)*2;
      float2 q0 = __ldg(&sw2[col]), q1 = __ldg(&sw2[col+1]);
      wx[j][0] = q0.x; wy[j][0] = q0.y;
      wx[j][1] = q1.x; wy[j][1] = q1.y;
      wl[j][0] = __ldg(&attw[col]); wl[j][1] = __ldg(&attw[col+1]);
    }
#pragma unroll
    for (int mt = 0; mt < 2; ++mt)
#pragma unroll
      for (int h = 0; h < 2; ++h) {
        int row = r0 + mw*32 + mt*16 + (lane >> 2) + h*8;
        float sx = 0.f, sy = 0.f, sl = 0.f;
#pragma unroll
        for (int j = 0; j < 4; ++j) {
          float v0 = acc[mt][j][h*2+0];
          float v1 = acc[mt][j][h*2+1];
          v0 = v0 / (1.f + __expf(-v0));
          v1 = v1 / (1.f + __expf(-v1));
          sx = fmaf(v0, wx[j][0], sx); sx = fmaf(v1, wx[j][1], sx);
          sy = fmaf(v0, wy[j][0], sy); sy = fmaf(v1, wy[j][1], sy);
          sl = fmaf(v0, wl[j][0], sl); sl = fmaf(v1, wl[j][1], sl);
        }
        sx += __shfl_xor_sync(0xffffffffu, sx, 1);
        sy += __shfl_xor_sync(0xffffffffu, sy, 1);
        sl += __shfl_xor_sync(0xffffffffu, sl, 1);
        sx += __shfl_xor_sync(0xffffffffu, sx, 2);
        sy += __shfl_xor_sync(0xffffffffu, sy, 2);
        sl += __shfl_xor_sync(0xffffffffu, sl, 2);
        if ((lane & 3) == 0) {
          float* o = Out + ((size_t)g*MTOT + row)*3;
          o[0] = sx; o[1] = sy; o[2] = sl;
        }
      }
  }
}

// mega: y<16 -> offset GEMM (single-pass bf16, N0=y*256); y==16 -> value proj
__global__ void __launch_bounds__(512, 1)
mega_gemm(const uint4* __restrict__ Qh,
          const uint4* __restrict__ Wh,
          const float* __restrict__ sow, const float* __restrict__ attw,
          float* __restrict__ pofa,
          const uint4* __restrict__ Ih, const uint4* __restrict__ Il,
          const uint4* __restrict__ Vh, const uint4* __restrict__ Vl,
          const float* __restrict__ vbias, __half* __restrict__ pval) {
  const int r0 = blockIdx.x * 128;
  if (blockIdx.y < 16)
    gemm1_body(Qh, Wh, sow, attw, pofa, r0, blockIdx.y*256);
  else
    gemm_body<2,2>(Ih, Il, Vh, Vl, vbias, pval, r0, 0);
}

template<int MODE, int NT>
__global__ void __launch_bounds__(512, 1)
gemm_mma(const uint4* __restrict__ Ah, const uint4* __restrict__ Al,
         const uint4* __restrict__ Bh, const uint4* __restrict__ Bl,
         const float* __restrict__ c0, void* __restrict__ OutV) {
  gemm_body<MODE,NT>(Ah, Al, Bh, Bl, c0, OutV, blockIdx.x*128, blockIdx.y*NT*128);
}

// ===========================================================================
// Sampling: one warp per (b,q,head); 2 points per warp via half2 lanes.
// ===========================================================================
__global__ void __launch_bounds__(256)
sample_kernel(const float* __restrict__ ref, const float* __restrict__ sob,
              const float* __restrict__ attb) {
  __shared__ float s_lx[NH][16], s_ly[NH][16], s_aw[NH][16];
  const int bq   = blockIdx.x;
  const int b    = bq / LEN;
  const int h    = threadIdx.x >> 5;
  const int lane = threadIdx.x & 31;
  const int p    = lane & 15;
  const int l    = p >> 2;

  const float SZ[4] = {64.f, 32.f, 16.f, 8.f};
  int g = h*16 + p;
  size_t ob = ((size_t)g*MTOT + bq)*3;
  float rx = g_offaw[ob+0], ry = g_offaw[ob+1], rl = g_offaw[ob+2];
  float inv = 1.f / SZ[l];
  float lx = ref[(size_t)bq*8 + l*2 + 0] + (rx + sob[g*2+0]) * inv;
  float ly = ref[(size_t)bq*8 + l*2 + 1] + (ry + sob[g*2+1]) * inv;
  float logit = rl + attb[g];

  float mx = logit;
#pragma unroll
  for (int off = 8; off; off >>= 1)
    mx = fmaxf(mx, __shfl_xor_sync(0xffffffffu, mx, off, 16));
  float e = __expf(logit - mx);
  float ssum = e;
#pragma unroll
  for (int off = 8; off; off >>= 1)
    ssum += __shfl_xor_sync(0xffffffffu, ssum, off, 16);
  float aw = e / ssum;

  if (lane < 16) { s_lx[h][p] = lx; s_ly[h][p] = ly; s_aw[h][p] = aw; }
  __syncwarp(0xffffffffu);

  const int ST[4]  = {0, 4096, 5120, 5376};
  const int SZI[4] = {64, 32, 16, 8};
  const int halfid = lane >> 4;
  const int dpair  = lane & 15;
  float ax = 0.f, ay = 0.f;
  const __half2* vb2 = reinterpret_cast<const __half2*>(g_value)
                     + (size_t)b*LEN*128 + h*16 + dpair;

#pragma unroll
  for (int t = 0; t < 8; ++t) {
    int pp = t*2 + halfid;
    int ll = pp >> 2;
    int S  = SZI[ll];
    float x = s_lx[h][pp]*(float)S - 0.5f;
    float y = s_ly[h][pp]*(float)S - 0.5f;
    float w = s_aw[h][pp];
    float fx = floorf(x), fy = floorf(y);
    int x0 = (int)fx, y0 = (int)fy;
    float wx = x - fx, wy = y - fy;
    const __half2* vl = vb2 + (size_t)ST[ll]*128;
    __half2 z = __floats2half2_rn(0.f, 0.f);
    __half2 v00 = z, v01 = z, v10 = z, v11 = z;
    bool xa = (x0   >= 0) && (x0   < S);
    bool xb = (x0+1 >= 0) && (x0+1 < S);
    bool ya = (y0   >= 0) && (y0   < S);
    bool yb = (y0+1 >= 0) && (y0+1 < S);
    if (xa && ya) v00 = vl[(size_t)(y0*S + x0  )*128];
    if (xb && ya) v01 = vl[(size_t)(y0*S + x0+1)*128];
    if (xa && yb) v10 = vl[(size_t)((y0+1)*S + x0  )*128];
    if (xb && yb) v11 = vl[(size_t)((y0+1)*S + x0+1)*128];
    float2 f00 = __half22float2(v00), f01 = __half22float2(v01);
    float2 f10 = __half22float2(v10), f11 = __half22float2(v11);
    float w00 = (1.f-wx)*(1.f-wy)*w, w01 = wx*(1.f-wy)*w;
    float w10 = (1.f-wx)*wy*w,       w11 = wx*wy*w;
    ax += f00.x*w00 + f01.x*w01 + f10.x*w10 + f11.x*w11;
    ay += f00.y*w00 + f01.y*w01 + f10.y*w10 + f11.y*w11;
  }
  ax += __shfl_xor_sync(0xffffffffu, ax, 16);
  ay += __shfl_xor_sync(0xffffffffu, ay, 16);

  if (lane < 16) {
    __nv_bfloat16 hx = __float2bfloat16_rn(ax);
    __nv_bfloat16 hy = __float2bfloat16_rn(ay);
    __nv_bfloat162 hi2(hx, hy);
    __nv_bfloat162 lo2(__float2bfloat16_rn(ax - __bfloat162float(hx)),
                       __float2bfloat16_rn(ay - __bfloat162float(hy)));
    size_t idx = (size_t)bq*128 + h*16 + dpair;
    reinterpret_cast<__nv_bfloat162*>(g_mh)[idx] = hi2;
    reinterpret_cast<__nv_bfloat162*>(g_ml)[idx] = lo2;
  }
}

// ===========================================================================
extern "C" void kernel_launch(void* const* d_in, const int* in_sizes, int n_in,
                              void* d_out, int out_size) {
  (void)in_sizes; (void)n_in; (void)out_size;
  const float* query  = (const float*)d_in[0];
  const float* ref    = (const float*)d_in[1];
  const float* inputf = (const float*)d_in[2];
  const float* oeW    = (const float*)d_in[4];
  const float* sow    = (const float*)d_in[5];
  const float* sob    = (const float*)d_in[6];
  const float* attW   = (const float*)d_in[7];
  const float* attb   = (const float*)d_in[8];
  const float* valW   = (const float*)d_in[9];
  const float* valb   = (const float*)d_in[10];
  const float* outW   = (const float*)d_in[11];
  const float* outb   = (const float*)d_in[12];
  float* out = (float*)d_out;

  uint4 *qh,*ifh,*ifl,*mh,*ml,*wembh,*vwh,*vwl,*owh,*owl;
  void *pval; float *pofa;
  cudaGetSymbolAddress((void**)&qh, g_qh);
  cudaGetSymbolAddress((void**)&ifh, g_ifh);   cudaGetSymbolAddress((void**)&ifl, g_ifl);
  cudaGetSymbolAddress((void**)&mh, g_mh);     cudaGetSymbolAddress((void**)&ml, g_ml);
  cudaGetSymbolAddress((void**)&wembh, g_wembh);
  cudaGetSymbolAddress((void**)&vwh, g_vwh);   cudaGetSymbolAddress((void**)&vwl, g_vwl);
  cudaGetSymbolAddress((void**)&owh, g_owh);   cudaGetSymbolAddress((void**)&owl, g_owl);
  cudaGetSymbolAddress((void**)&pval, g_value);
  cudaGetSymbolAddress((void**)&pofa, g_offaw);

  const int dynsmem = 131072 + 3*32768;  // 224 KB (covers both bodies)
  cudaFuncSetAttribute(mega_gemm, cudaFuncAttributeMaxDynamicSharedMemorySize, dynsmem);
  cudaFuncSetAttribute(gemm_mma<0,2>, cudaFuncAttributeMaxDynamicSharedMemorySize, dynsmem);

  const int n4 = MTOT*64;
  split_hi<<<n4/256, 256>>>(reinterpret_cast<const float4*>(query),
                            reinterpret_cast<__nv_bfloat162*>(qh), n4);       // 0
  split_hi<<<1024, 256>>>(reinterpret_cast<const float4*>(oeW),
                          reinterpret_cast<__nv_bfloat162*>(wembh), 4096*64); // 1
  split_ifw<<<5568, 256>>>(reinterpret_cast<const float4*>(inputf),
                           reinterpret_cast<__nv_bfloat162*>(ifh),
                           reinterpret_cast<__nv_bfloat162*>(ifl),
                           reinterpret_cast<const float4*>(valW),
                           reinterpret_cast<__nv_bfloat162*>(vwh),
                           reinterpret_cast<__nv_bfloat162*>(vwl),
                           reinterpret_cast<const float4*>(outW),
                           reinterpret_cast<__nv_bfloat162*>(owh),
                           reinterpret_cast<__nv_bfloat162*>(owl));           // 2
  mega_gemm<<<dim3(MTOT/128,17), 512, dynsmem>>>(qh, wembh, sow, attW, pofa,
                                                 ifh, ifl, vwh, vwl,
                                                 valb, (__half*)pval);        // 3
  sample_kernel<<<MTOT, 256>>>(ref, sob, attb);                               // 4
  gemm_mma<0,2><<<dim3(MTOT/128,1), 512, dynsmem>>>(mh, ml, owh, owl,
                                                    outb, out);               // 5
}

// round 12
// speedup vs baseline: 1.7747x; 1.7747x over previous
#include <cuda_runtime.h>
#include <cuda_bf16.h>
#include <cuda_fp16.h>
#include <math.h>
#include <stdint.h>

#define NB   4
#define LEN  5440
#define MTOT (NB*LEN)      // 21760
#define DM   256
#define NH   8
#define NG   128

// ===========================================================================
// Scratch (allocation-free __device__ globals)
// ===========================================================================
__device__ uint4 g_qh[MTOT*32];                      // query bf16 hi (row-major)
__device__ uint4 g_ifh[MTOT*32], g_ifl[MTOT*32];     // input_flatten split
__device__ uint4 g_mh[MTOT*32],  g_ml[MTOT*32];      // mix (sample output) split
__device__ uint4 g_wembh[4096*32];                   // offset-embed W bf16 hi
__device__ uint4 g_vwh[256*32],   g_vwl[256*32];     // value W split
__device__ uint4 g_owh[256*32],   g_owl[256*32];     // out W split
__device__ __half g_value[MTOT*DM];                  // value projection (fp16)
__device__ float g_offaw[(size_t)NG*MTOT*3];         // [group][row][3]

// ===========================================================================
__device__ __forceinline__ uint32_t s2u(const void* p) {
  uint32_t a;
  asm("{ .reg .u64 t; cvta.to.shared.u64 t, %1; cvt.u32.u64 %0, t; }" : "=r"(a) : "l"(p));
  return a;
}
__device__ __forceinline__ void ldsm4(uint32_t& r0, uint32_t& r1, uint32_t& r2,
                                      uint32_t& r3, uint32_t addr) {
  asm volatile("ldmatrix.sync.aligned.m8n8.x4.shared.b16 {%0,%1,%2,%3}, [%4];"
               : "=r"(r0), "=r"(r1), "=r"(r2), "=r"(r3) : "r"(addr));
}
__device__ __forceinline__ void mma16816(float& c0, float& c1, float& c2, float& c3,
                                         uint32_t a0, uint32_t a1, uint32_t a2, uint32_t a3,
                                         uint32_t b0, uint32_t b1) {
  asm volatile("mma.sync.aligned.m16n8k16.row.col.f32.bf16.bf16.f32 "
               "{%0,%1,%2,%3}, {%4,%5,%6,%7}, {%8,%9}, {%0,%1,%2,%3};"
               : "+f"(c0), "+f"(c1), "+f"(c2), "+f"(c3)
               : "r"(a0), "r"(a1), "r"(a2), "r"(a3), "r"(b0), "r"(b1));
}
// silu via tanh.approx: v*sigmoid(v) = 0.5*v*(1+tanh(v/2)). 1 MUFU + mul + fma.
__device__ __forceinline__ float silu_t(float v) {
  float t;
  asm("tanh.approx.f32 %0, %1;" : "=f"(t) : "f"(v*0.5f));
  return fmaf(0.5f*v, t, 0.5f*v);
}
#define CP_ASYNC16(dst, src) \
  asm volatile("cp.async.cg.shared.global [%0], [%1], 16;" :: "r"(dst), "l"(src))
#define CP_COMMIT() asm volatile("cp.async.commit_group;")
#define CP_WAIT(n)  asm volatile("cp.async.wait_group %0;" :: "n"(n) : "memory")

// ===========================================================================
// prep kernels
// ===========================================================================
__device__ __forceinline__ void split_body(const float4* __restrict__ in,
                                           __nv_bfloat162* __restrict__ hi,
                                           __nv_bfloat162* __restrict__ lo, int i) {
  float4 v = in[i];
  __nv_bfloat16 hx = __float2bfloat16_rn(v.x);
  __nv_bfloat16 hy = __float2bfloat16_rn(v.y);
  __nv_bfloat16 hz = __float2bfloat16_rn(v.z);
  __nv_bfloat16 hw = __float2bfloat16_rn(v.w);
  hi[2*i+0] = __nv_bfloat162(hx, hy);
  hi[2*i+1] = __nv_bfloat162(hz, hw);
  lo[2*i+0] = __nv_bfloat162(__float2bfloat16_rn(v.x - __bfloat162float(hx)),
                             __float2bfloat16_rn(v.y - __bfloat162float(hy)));
  lo[2*i+1] = __nv_bfloat162(__float2bfloat16_rn(v.z - __bfloat162float(hz)),
                             __float2bfloat16_rn(v.w - __bfloat162float(hw)));
}

__global__ void __launch_bounds__(256)
split_hi(const float4* __restrict__ in, __nv_bfloat162* __restrict__ hi, int n4) {
  int i = blockIdx.x*256 + threadIdx.x;
  if (i >= n4) return;
  float4 v = in[i];
  hi[2*i+0] = __nv_bfloat162(__float2bfloat16_rn(v.x), __float2bfloat16_rn(v.y));
  hi[2*i+1] = __nv_bfloat162(__float2bfloat16_rn(v.z), __float2bfloat16_rn(v.w));
}

// fused split: input_flatten (0..5439) + valW (5440..5503) + outW (5504..5567)
__global__ void __launch_bounds__(256)
split_ifw(const float4* __restrict__ inf, __nv_bfloat162* __restrict__ ifh,
          __nv_bfloat162* __restrict__ ifl,
          const float4* __restrict__ w1, __nv_bfloat162* __restrict__ h1,
          __nv_bfloat162* __restrict__ l1,
          const float4* __restrict__ w2, __nv_bfloat162* __restrict__ h2,
          __nv_bfloat162* __restrict__ l2) {
  int b = blockIdx.x;
  if (b < 5440)      split_body(inf, ifh, ifl, b*256 + threadIdx.x);
  else if (b < 5504) split_body(w1, h1, l1, (b-5440)*256 + threadIdx.x);
  else               split_body(w2, h2, l2, (b-5504)*256 + threadIdx.x);
}

// ===========================================================================
// 3-term split-bf16 GEMM body (value / out projections — precision path).
// ===========================================================================
template<int MODE, int NT>
__device__ __forceinline__ void gemm_body(
    const uint4* __restrict__ Ah, const uint4* __restrict__ Al,
    const uint4* __restrict__ Bh, const uint4* __restrict__ Bl,
    const float* __restrict__ c0,
    void* __restrict__ OutV, int r0, int N0) {
  extern __shared__ char dsm[];
  const uint32_t as = s2u(dsm);            // A: 128 rows x 1024B = 131072
  const uint32_t bsb = as + 131072u;       // B: 3 x 32768 (hi 16KB | lo 16KB)
  const int tid = threadIdx.x;
  const int wid = tid >> 5, lane = tid & 31;
  const int mw = wid & 3, nw = wid >> 2;

#pragma unroll
  for (int it = 0; it < 16; ++it) {
    int i = it*512 + tid;
    int r = i >> 6, u = i & 63;
    int half = u >> 5, uu = u & 31;
    int s = (half << 2) + (uu >> 3), c = uu & 7;
    const uint4* src = (half ? Al : Ah) + (size_t)(r0 + r)*32 + uu;
    uint32_t dst = as + (uint32_t)r*1024u + (uint32_t)s*128u + (uint32_t)((c ^ (r & 7))*16);
    CP_ASYNC16(dst, src);
  }
  CP_COMMIT();

  const int lA = mw*32 + (lane & 15);
  const int jj = lane >> 4;
  const int nB = nw*32 + (lane & 15);
  const uint32_t pA = as + (uint32_t)lA*1024u;
  const int swA = lA & 7, swB = nB & 7;

  for (int nt = 0; nt < NT; ++nt) {
    float acc[2][4][4];
#pragma unroll
    for (int a = 0; a < 2; ++a)
#pragma unroll
      for (int b = 0; b < 4; ++b)
#pragma unroll
        for (int d = 0; d < 4; ++d) acc[a][b][d] = 0.f;

    const int nrow0 = N0 + nt*128;

    auto prefetchC4 = [&](int c4, int bi) {
#pragma unroll
      for (int it = 0; it < 4; ++it) {
        int i = it*512 + tid;
        int n = i >> 4, u = i & 15;
        int sub = u >> 3, c = u & 7;
        const uint4* src = (sub ? Bl : Bh) + (size_t)(nrow0 + n)*32 + c4*8 + c;
        uint32_t dst = bsb + (uint32_t)bi*32768u + (uint32_t)sub*16384u
                     + (uint32_t)n*128u + (uint32_t)((c ^ (n & 7))*16);
        CP_ASYNC16(dst, src);
      }
      CP_COMMIT();
    };

    prefetchC4(0, 0);
    prefetchC4(1, 1);

#pragma unroll
    for (int c4 = 0; c4 < 4; ++c4) {
      if (c4 == 3) { CP_WAIT(0); } else { CP_WAIT(1); }
      __syncthreads();
      if (c4 + 2 < 4) prefetchC4(c4 + 2, (c4 + 2) % 3);

      const uint32_t bs  = bsb + (uint32_t)(c4 % 3)*32768u;
      const uint32_t aBh = pA + (uint32_t)c4*128u;
      const uint32_t aBl = pA + (uint32_t)(4 + c4)*128u;
#pragma unroll
      for (int ks = 0; ks < 4; ++ks) {
        const int cc = ks*2 + jj;
        const uint32_t csw = (uint32_t)((cc ^ swA)*16);
        uint32_t ah[2][4], al[2][4];
        ldsm4(ah[0][0], ah[0][1], ah[0][2], ah[0][3], aBh + csw);
        ldsm4(ah[1][0], ah[1][1], ah[1][2], ah[1][3], aBh + 16384u + csw);
        ldsm4(al[0][0], al[0][1], al[0][2], al[0][3], aBl + csw);
        ldsm4(al[1][0], al[1][1], al[1][2], al[1][3], aBl + 16384u + csw);
        const uint32_t bsw = (uint32_t)((cc ^ swB)*16);
        uint32_t bh[2][4], bl[2][4];
#pragma unroll
        for (int qt = 0; qt < 2; ++qt) {
          ldsm4(bh[qt][0], bh[qt][1], bh[qt][2], bh[qt][3],
                bs + (uint32_t)nB*128u + (uint32_t)qt*2048u + bsw);
          ldsm4(bl[qt][0], bl[qt][1], bl[qt][2], bl[qt][3],
                bs + 16384u + (uint32_t)nB*128u + (uint32_t)qt*2048u + bsw);
        }
#pragma unroll
        for (int qt = 0; qt < 2; ++qt)
#pragma unroll
          for (int mt = 0; mt < 2; ++mt) {
            mma16816(acc[mt][qt*2  ][0], acc[mt][qt*2  ][1], acc[mt][qt*2  ][2], acc[mt][qt*2  ][3],
                     ah[mt][0], ah[mt][1], ah[mt][2], ah[mt][3], bh[qt][0], bh[qt][2]);
            mma16816(acc[mt][qt*2+1][0], acc[mt][qt*2+1][1], acc[mt][qt*2+1][2], acc[mt][qt*2+1][3],
                     ah[mt][0], ah[mt][1], ah[mt][2], ah[mt][3], bh[qt][1], bh[qt][3]);
          }
#pragma unroll
        for (int qt = 0; qt < 2; ++qt)
#pragma unroll
          for (int mt = 0; mt < 2; ++mt) {
            mma16816(acc[mt][qt*2  ][0], acc[mt][qt*2  ][1], acc[mt][qt*2  ][2], acc[mt][qt*2  ][3],
                     al[mt][0], al[mt][1], al[mt][2], al[mt][3], bh[qt][0], bh[qt][2]);
            mma16816(acc[mt][qt*2+1][0], acc[mt][qt*2+1][1], acc[mt][qt*2+1][2], acc[mt][qt*2+1][3],
                     al[mt][0], al[mt][1], al[mt][2], al[mt][3], bh[qt][1], bh[qt][3]);
          }
#pragma unroll
        for (int qt = 0; qt < 2; ++qt)
#pragma unroll
          for (int mt = 0; mt < 2; ++mt) {
            mma16816(acc[mt][qt*2  ][0], acc[mt][qt*2  ][1], acc[mt][qt*2  ][2], acc[mt][qt*2  ][3],
                     ah[mt][0], ah[mt][1], ah[mt][2], ah[mt][3], bl[qt][0], bl[qt][2]);
            mma16816(acc[mt][qt*2+1][0], acc[mt][qt*2+1][1], acc[mt][qt*2+1][2], acc[mt][qt*2+1][3],
                     ah[mt][0], ah[mt][1], ah[mt][2], ah[mt][3], bl[qt][1], bl[qt][3]);
          }
      }
    }
    __syncthreads();

#pragma unroll
    for (int mt = 0; mt < 2; ++mt)
#pragma unroll
      for (int h = 0; h < 2; ++h) {
        int row = r0 + mw*32 + mt*16 + (lane >> 2) + h*8;
#pragma unroll
        for (int j = 0; j < 4; ++j) {
          int col = nt*128 + nw*32 + j*8 + (lane & 3)*2;
          float ox = acc[mt][j][h*2+0] + c0[col];
          float oy = acc[mt][j][h*2+1] + c0[col+1];
          if (MODE == 0) {
            float2 o; o.x = ox; o.y = oy;
            *reinterpret_cast<float2*>((float*)OutV + (size_t)row*256 + col) = o;
          } else {
            __half2 o = __floats2half2_rn(ox, oy);
            *reinterpret_cast<__half2*>((__half*)OutV + (size_t)row*256 + col) = o;
          }
        }
      }
  }
}

// ===========================================================================
// Single-pass bf16 GEMM body (offset path — error-tolerant).
// A hi-only resident (64KB); B hi-only 3 x 16KB chunks. NT=2.
// Epilogue: silu(tanh) + group dot -> g_offaw.
// ===========================================================================
__device__ __forceinline__ void gemm1_body(
    const uint4* __restrict__ Ah, const uint4* __restrict__ Bh,
    const float* __restrict__ sow, const float* __restrict__ attw,
    float* __restrict__ Out, int r0, int N0) {
  extern __shared__ char dsm[];
  const uint32_t as = s2u(dsm);            // A: 128 rows x 512B = 65536
  const uint32_t bsb = as + 65536u;        // B: 3 x 16384
  const int tid = threadIdx.x;
  const int wid = tid >> 5, lane = tid & 31;
  const int mw = wid & 3, nw = wid >> 2;

#pragma unroll
  for (int it = 0; it < 8; ++it) {
    int i = it*512 + tid;
    int r = i >> 5, uu = i & 31;
    int s = uu >> 3, c = uu & 7;
    const uint4* src = Ah + (size_t)(r0 + r)*32 + uu;
    uint32_t dst = as + (uint32_t)r*512u + (uint32_t)s*128u + (uint32_t)((c ^ (r & 7))*16);
    CP_ASYNC16(dst, src);
  }
  CP_COMMIT();

  const int lA = mw*32 + (lane & 15);
  const int jj = lane >> 4;
  const int nB = nw*32 + (lane & 15);
  const uint32_t pA = as + (uint32_t)lA*512u;
  const int swA = lA & 7, swB = nB & 7;

  for (int nt = 0; nt < 2; ++nt) {
    float acc[2][4][4];
#pragma unroll
    for (int a = 0; a < 2; ++a)
#pragma unroll
      for (int b = 0; b < 4; ++b)
#pragma unroll
        for (int d = 0; d < 4; ++d) acc[a][b][d] = 0.f;

    const int nrow0 = N0 + nt*128;

    auto prefetchC4 = [&](int c4, int bi) {
#pragma unroll
      for (int it = 0; it < 2; ++it) {
        int i = it*512 + tid;
        int n = i >> 3, c = i & 7;
        const uint4* src = Bh + (size_t)(nrow0 + n)*32 + c4*8 + c;
        uint32_t dst = bsb + (uint32_t)bi*16384u
                     + (uint32_t)n*128u + (uint32_t)((c ^ (n & 7))*16);
        CP_ASYNC16(dst, src);
      }
      CP_COMMIT();
    };

    prefetchC4(0, 0);
    prefetchC4(1, 1);

#pragma unroll
    for (int c4 = 0; c4 < 4; ++c4) {
      if (c4 == 3) { CP_WAIT(0); } else { CP_WAIT(1); }
      __syncthreads();
      if (c4 + 2 < 4) prefetchC4(c4 + 2, (c4 + 2) % 3);

      const uint32_t bs = bsb + (uint32_t)(c4 % 3)*16384u;
      const uint32_t aB = pA + (uint32_t)c4*128u;
#pragma unroll
      for (int ks = 0; ks < 4; ++ks) {
        const int cc = ks*2 + jj;
        const uint32_t csw = (uint32_t)((cc ^ swA)*16);
        uint32_t ah[2][4];
        ldsm4(ah[0][0], ah[0][1], ah[0][2], ah[0][3], aB + csw);
        ldsm4(ah[1][0], ah[1][1], ah[1][2], ah[1][3], aB + 8192u + csw);
        const uint32_t bsw = (uint32_t)((cc ^ swB)*16);
        uint32_t bh[2][4];
#pragma unroll
        for (int qt = 0; qt < 2; ++qt)
          ldsm4(bh[qt][0], bh[qt][1], bh[qt][2], bh[qt][3],
                bs + (uint32_t)nB*128u + (uint32_t)qt*2048u + bsw);
#pragma unroll
        for (int qt = 0; qt < 2; ++qt)
#pragma unroll
          for (int mt = 0; mt < 2; ++mt) {
            mma16816(acc[mt][qt*2  ][0], acc[mt][qt*2  ][1], acc[mt][qt*2  ][2], acc[mt][qt*2  ][3],
                     ah[mt][0], ah[mt][1], ah[mt][2], ah[mt][3], bh[qt][0], bh[qt][2]);
            mma16816(acc[mt][qt*2+1][0], acc[mt][qt*2+1][1], acc[mt][qt*2+1][2], acc[mt][qt*2+1][3],
                     ah[mt][0], ah[mt][1], ah[mt][2], ah[mt][3], bh[qt][1], bh[qt][3]);
          }
      }
    }
    __syncthreads();

    // epilogue: silu (tanh.approx) + group-of-32 dot
    const float2* sw2 = reinterpret_cast<const float2*>(sow);
    int g = (N0 + nt*128 + nw*32) >> 5;
    float wx[4][2], wy[4][2], wl[4][2];
#pragma unroll
    for (int j = 0; j < 4; ++j) {
      int col = g*32 + j*8 + (lane & 3)*2;
      float2 q0 = __ldg(&sw2[col]), q1 = __ldg(&sw2[col+1]);
      wx[j][0] = q0.x; wy[j][0] = q0.y;
      wx[j][1] = q1.x; wy[j][1] = q1.y;
      wl[j][0] = __ldg(&attw[col]); wl[j][1] = __ldg(&attw[col+1]);
    }
#pragma unroll
    for (int mt = 0; mt < 2; ++mt)
#pragma unroll
      for (int h = 0; h < 2; ++h) {
        int row = r0 + mw*32 + mt*16 + (lane >> 2) + h*8;
        float sx = 0.f, sy = 0.f, sl = 0.f;
#pragma unroll
        for (int j = 0; j < 4; ++j) {
          float v0 = silu_t(acc[mt][j][h*2+0]);
          float v1 = silu_t(acc[mt][j][h*2+1]);
          sx = fmaf(v0, wx[j][0], sx); sx = fmaf(v1, wx[j][1], sx);
          sy = fmaf(v0, wy[j][0], sy); sy = fmaf(v1, wy[j][1], sy);
          sl = fmaf(v0, wl[j][0], sl); sl = fmaf(v1, wl[j][1], sl);
        }
        sx += __shfl_xor_sync(0xffffffffu, sx, 1);
        sy += __shfl_xor_sync(0xffffffffu, sy, 1);
        sl += __shfl_xor_sync(0xffffffffu, sl, 1);
        sx += __shfl_xor_sync(0xffffffffu, sx, 2);
        sy += __shfl_xor_sync(0xffffffffu, sy, 2);
        sl += __shfl_xor_sync(0xffffffffu, sl, 2);
        if ((lane & 3) == 0) {
          float* o = Out + ((size_t)g*MTOT + row)*3;
          o[0] = sx; o[1] = sy; o[2] = sl;
        }
      }
  }
}

// mega: y==0 -> value proj (slow 3-term, scheduled FIRST); y=1..16 -> offset
__global__ void __launch_bounds__(512, 1)
mega_gemm(const uint4* __restrict__ Qh,
          const uint4* __restrict__ Wh,
          const float* __restrict__ sow, const float* __restrict__ attw,
          float* __restrict__ pofa,
          const uint4* __restrict__ Ih, const uint4* __restrict__ Il,
          const uint4* __restrict__ Vh, const uint4* __restrict__ Vl,
          const float* __restrict__ vbias, __half* __restrict__ pval) {
  const int r0 = blockIdx.x * 128;
  if (blockIdx.y == 0)
    gemm_body<2,2>(Ih, Il, Vh, Vl, vbias, pval, r0, 0);
  else
    gemm1_body(Qh, Wh, sow, attw, pofa, r0, (blockIdx.y-1)*256);
}

template<int MODE, int NT>
__global__ void __launch_bounds__(512, 1)
gemm_mma(const uint4* __restrict__ Ah, const uint4* __restrict__ Al,
         const uint4* __restrict__ Bh, const uint4* __restrict__ Bl,
         const float* __restrict__ c0, void* __restrict__ OutV) {
  gemm_body<MODE,NT>(Ah, Al, Bh, Bl, c0, OutV, blockIdx.x*128, blockIdx.y*NT*128);
}

// ===========================================================================
// Sampling: one warp per (b,q,head); 2 points per warp via half2 lanes.
// ===========================================================================
__global__ void __launch_bounds__(256)
sample_kernel(const float* __restrict__ ref, const float* __restrict__ sob,
              const float* __restrict__ attb) {
  __shared__ float s_lx[NH][16], s_ly[NH][16], s_aw[NH][16];
  const int bq   = blockIdx.x;
  const int b    = bq / LEN;
  const int h    = threadIdx.x >> 5;
  const int lane = threadIdx.x & 31;
  const int p    = lane & 15;
  const int l    = p >> 2;

  const float SZ[4] = {64.f, 32.f, 16.f, 8.f};
  int g = h*16 + p;
  size_t ob = ((size_t)g*MTOT + bq)*3;
  float rx = g_offaw[ob+0], ry = g_offaw[ob+1], rl = g_offaw[ob+2];
  float inv = 1.f / SZ[l];
  float lx = ref[(size_t)bq*8 + l*2 + 0] + (rx + sob[g*2+0]) * inv;
  float ly = ref[(size_t)bq*8 + l*2 + 1] + (ry + sob[g*2+1]) * inv;
  float logit = rl + attb[g];

  float mx = logit;
#pragma unroll
  for (int off = 8; off; off >>= 1)
    mx = fmaxf(mx, __shfl_xor_sync(0xffffffffu, mx, off, 16));
  float e = __expf(logit - mx);
  float ssum = e;
#pragma unroll
  for (int off = 8; off; off >>= 1)
    ssum += __shfl_xor_sync(0xffffffffu, ssum, off, 16);
  float aw = e / ssum;

  if (lane < 16) { s_lx[h][p] = lx; s_ly[h][p] = ly; s_aw[h][p] = aw; }
  __syncwarp(0xffffffffu);

  const int ST[4]  = {0, 4096, 5120, 5376};
  const int SZI[4] = {64, 32, 16, 8};
  const int halfid = lane >> 4;
  const int dpair  = lane & 15;
  float ax = 0.f, ay = 0.f;
  const __half2* vb2 = reinterpret_cast<const __half2*>(g_value)
                     + (size_t)b*LEN*128 + h*16 + dpair;

#pragma unroll
  for (int t = 0; t < 8; ++t) {
    int pp = t*2 + halfid;
    int ll = pp >> 2;
    int S  = SZI[ll];
    float x = s_lx[h][pp]*(float)S - 0.5f;
    float y = s_ly[h][pp]*(float)S - 0.5f;
    float w = s_aw[h][pp];
    float fx = floorf(x), fy = floorf(y);
    int x0 = (int)fx, y0 = (int)fy;
    float wx = x - fx, wy = y - fy;
    const __half2* vl = vb2 + (size_t)ST[ll]*128;
    __half2 z = __floats2half2_rn(0.f, 0.f);
    __half2 v00 = z, v01 = z, v10 = z, v11 = z;
    bool xa = (x0   >= 0) && (x0   < S);
    bool xb = (x0+1 >= 0) && (x0+1 < S);
    bool ya = (y0   >= 0) && (y0   < S);
    bool yb = (y0+1 >= 0) && (y0+1 < S);
    if (xa && ya) v00 = vl[(size_t)(y0*S + x0  )*128];
    if (xb && ya) v01 = vl[(size_t)(y0*S + x0+1)*128];
    if (xa && yb) v10 = vl[(size_t)((y0+1)*S + x0  )*128];
    if (xb && yb) v11 = vl[(size_t)((y0+1)*S + x0+1)*128];
    float2 f00 = __half22float2(v00), f01 = __half22float2(v01);
    float2 f10 = __half22float2(v10), f11 = __half22float2(v11);
    float w00 = (1.f-wx)*(1.f-wy)*w, w01 = wx*(1.f-wy)*w;
    float w10 = (1.f-wx)*wy*w,       w11 = wx*wy*w;
    ax += f00.x*w00 + f01.x*w01 + f10.x*w10 + f11.x*w11;
    ay += f00.y*w00 + f01.y*w01 + f10.y*w10 + f11.y*w11;
  }
  ax += __shfl_xor_sync(0xffffffffu, ax, 16);
  ay += __shfl_xor_sync(0xffffffffu, ay, 16);

  if (lane < 16) {
    __nv_bfloat16 hx = __float2bfloat16_rn(ax);
    __nv_bfloat16 hy = __float2bfloat16_rn(ay);
    __nv_bfloat162 hi2(hx, hy);
    __nv_bfloat162 lo2(__float2bfloat16_rn(ax - __bfloat162float(hx)),
                       __float2bfloat16_rn(ay - __bfloat162float(hy)));
    size_t idx = (size_t)bq*128 + h*16 + dpair;
    reinterpret_cast<__nv_bfloat162*>(g_mh)[idx] = hi2;
    reinterpret_cast<__nv_bfloat162*>(g_ml)[idx] = lo2;
  }
}

// ===========================================================================
extern "C" void kernel_launch(void* const* d_in, const int* in_sizes, int n_in,
                              void* d_out, int out_size) {
  (void)in_sizes; (void)n_in; (void)out_size;
  const float* query  = (const float*)d_in[0];
  const float* ref    = (const float*)d_in[1];
  const float* inputf = (const float*)d_in[2];
  const float* oeW    = (const float*)d_in[4];
  const float* sow    = (const float*)d_in[5];
  const float* sob    = (const float*)d_in[6];
  const float* attW   = (const float*)d_in[7];
  const float* attb   = (const float*)d_in[8];
  const float* valW   = (const float*)d_in[9];
  const float* valb   = (const float*)d_in[10];
  const float* outW   = (const float*)d_in[11];
  const float* outb   = (const float*)d_in[12];
  float* out = (float*)d_out;

  uint4 *qh,*ifh,*ifl,*mh,*ml,*wembh,*vwh,*vwl,*owh,*owl;
  void *pval; float *pofa;
  cudaGetSymbolAddress((void**)&qh, g_qh);
  cudaGetSymbolAddress((void**)&ifh, g_ifh);   cudaGetSymbolAddress((void**)&ifl, g_ifl);
  cudaGetSymbolAddress((void**)&mh, g_mh);     cudaGetSymbolAddress((void**)&ml, g_ml);
  cudaGetSymbolAddress((void**)&wembh, g_wembh);
  cudaGetSymbolAddress((void**)&vwh, g_vwh);   cudaGetSymbolAddress((void**)&vwl, g_vwl);
  cudaGetSymbolAddress((void**)&owh, g_owh);   cudaGetSymbolAddress((void**)&owl, g_owl);
  cudaGetSymbolAddress((void**)&pval, g_value);
  cudaGetSymbolAddress((void**)&pofa, g_offaw);

  const int dynsmem = 131072 + 3*32768;  // 224 KB (covers both bodies)
  cudaFuncSetAttribute(mega_gemm, cudaFuncAttributeMaxDynamicSharedMemorySize, dynsmem);
  cudaFuncSetAttribute(gemm_mma<0,2>, cudaFuncAttributeMaxDynamicSharedMemorySize, dynsmem);

  const int n4 = MTOT*64;
  split_hi<<<n4/256, 256>>>(reinterpret_cast<const float4*>(query),
                            reinterpret_cast<__nv_bfloat162*>(qh), n4);       // 0
  split_hi<<<1024, 256>>>(reinterpret_cast<const float4*>(oeW),
                          reinterpret_cast<__nv_bfloat162*>(wembh), 4096*64); // 1
  split_ifw<<<5568, 256>>>(reinterpret_cast<const float4*>(inputf),
                           reinterpret_cast<__nv_bfloat162*>(ifh),
                           reinterpret_cast<__nv_bfloat162*>(ifl),
                           reinterpret_cast<const float4*>(valW),
                           reinterpret_cast<__nv_bfloat162*>(vwh),
                           reinterpret_cast<__nv_bfloat162*>(vwl),
                           reinterpret_cast<const float4*>(outW),
                           reinterpret_cast<__nv_bfloat162*>(owh),
                           reinterpret_cast<__nv_bfloat162*>(owl));           // 2
  mega_gemm<<<dim3(MTOT/128,17), 512, dynsmem>>>(qh, wembh, sow, attW, pofa,
                                                 ifh, ifl, vwh, vwl,
                                                 valb, (__half*)pval);        // 3
  sample_kernel<<<MTOT, 256>>>(ref, sob, attb);                               // 4
  gemm_mma<0,2><<<dim3(MTOT/128,1), 512, dynsmem>>>(mh, ml, owh, owl,
                                                    outb, out);               // 5
}

// round 15
// speedup vs baseline: 1.8319x; 1.0323x over previous
#include <cuda_runtime.h>
#include <cuda_bf16.h>
#include <cuda_fp16.h>
#include <math.h>
#include <stdint.h>

#define NB   4
#define LEN  5440
#define MTOT (NB*LEN)      // 21760
#define DM   256
#define NH   8
#define NG   128

// ===========================================================================
// Scratch (allocation-free __device__ globals)
// ===========================================================================
__device__ uint4 g_qh[MTOT*32];                      // query bf16 hi (row-major)
__device__ uint4 g_ifh[MTOT*32], g_ifl[MTOT*32];     // input_flatten split
__device__ uint4 g_mh[MTOT*32],  g_ml[MTOT*32];      // mix (sample output) split
__device__ uint4 g_wembh[4096*32];                   // offset-embed W bf16 hi
__device__ uint4 g_vwh[256*32],   g_vwl[256*32];     // value W split
__device__ uint4 g_owh[256*32],   g_owl[256*32];     // out W split
__device__ __half g_value[MTOT*DM];                  // value projection (fp16)
__device__ float g_offaw[(size_t)NG*MTOT*3];         // [group][row][3]

// ===========================================================================
__device__ __forceinline__ uint32_t s2u(const void* p) {
  uint32_t a;
  asm("{ .reg .u64 t; cvta.to.shared.u64 t, %1; cvt.u32.u64 %0, t; }" : "=r"(a) : "l"(p));
  return a;
}
__device__ __forceinline__ void ldsm4(uint32_t& r0, uint32_t& r1, uint32_t& r2,
                                      uint32_t& r3, uint32_t addr) {
  asm volatile("ldmatrix.sync.aligned.m8n8.x4.shared.b16 {%0,%1,%2,%3}, [%4];"
               : "=r"(r0), "=r"(r1), "=r"(r2), "=r"(r3) : "r"(addr));
}
__device__ __forceinline__ void mma16816(float& c0, float& c1, float& c2, float& c3,
                                         uint32_t a0, uint32_t a1, uint32_t a2, uint32_t a3,
                                         uint32_t b0, uint32_t b1) {
  asm volatile("mma.sync.aligned.m16n8k16.row.col.f32.bf16.bf16.f32 "
               "{%0,%1,%2,%3}, {%4,%5,%6,%7}, {%8,%9}, {%0,%1,%2,%3};"
               : "+f"(c0), "+f"(c1), "+f"(c2), "+f"(c3)
               : "r"(a0), "r"(a1), "r"(a2), "r"(a3), "r"(b0), "r"(b1));
}
// silu via tanh.approx: v*sigmoid(v) = 0.5*v*(1+tanh(v/2)). 1 MUFU + mul + fma.
__device__ __forceinline__ float silu_t(float v) {
  float t;
  asm("tanh.approx.f32 %0, %1;" : "=f"(t) : "f"(v*0.5f));
  return fmaf(0.5f*v, t, 0.5f*v);
}
#define CP_ASYNC16(dst, src) \
  asm volatile("cp.async.cg.shared.global [%0], [%1], 16;" :: "r"(dst), "l"(src))
#define CP_COMMIT() asm volatile("cp.async.commit_group;")
#define CP_WAIT(n)  asm volatile("cp.async.wait_group %0;" :: "n"(n) : "memory")

// ===========================================================================
// prep kernels
// ===========================================================================
__device__ __forceinline__ void split_body(const float4* __restrict__ in,
                                           __nv_bfloat162* __restrict__ hi,
                                           __nv_bfloat162* __restrict__ lo, int i) {
  float4 v = in[i];
  __nv_bfloat16 hx = __float2bfloat16_rn(v.x);
  __nv_bfloat16 hy = __float2bfloat16_rn(v.y);
  __nv_bfloat16 hz = __float2bfloat16_rn(v.z);
  __nv_bfloat16 hw = __float2bfloat16_rn(v.w);
  hi[2*i+0] = __nv_bfloat162(hx, hy);
  hi[2*i+1] = __nv_bfloat162(hz, hw);
  lo[2*i+0] = __nv_bfloat162(__float2bfloat16_rn(v.x - __bfloat162float(hx)),
                             __float2bfloat16_rn(v.y - __bfloat162float(hy)));
  lo[2*i+1] = __nv_bfloat162(__float2bfloat16_rn(v.z - __bfloat162float(hz)),
                             __float2bfloat16_rn(v.w - __bfloat162float(hw)));
}

__device__ __forceinline__ void hi_body(const float4* __restrict__ in,
                                        __nv_bfloat162* __restrict__ hi, int i) {
  float4 v = in[i];
  hi[2*i+0] = __nv_bfloat162(__float2bfloat16_rn(v.x), __float2bfloat16_rn(v.y));
  hi[2*i+1] = __nv_bfloat162(__float2bfloat16_rn(v.z), __float2bfloat16_rn(v.w));
}

// one launch: query hi (0..5439), oeW hi (5440..6463), input_flatten split
// (6464..11903), valW split (11904..11967)
__global__ void __launch_bounds__(256)
split_all(const float4* __restrict__ q,   __nv_bfloat162* __restrict__ qh,
          const float4* __restrict__ oew, __nv_bfloat162* __restrict__ wembh,
          const float4* __restrict__ inf, __nv_bfloat162* __restrict__ ifh,
          __nv_bfloat162* __restrict__ ifl,
          const float4* __restrict__ vw,  __nv_bfloat162* __restrict__ vwh,
          __nv_bfloat162* __restrict__ vwl) {
  int b = blockIdx.x;
  if (b < 5440)       hi_body(q, qh, b*256 + threadIdx.x);
  else if (b < 6464)  hi_body(oew, wembh, (b-5440)*256 + threadIdx.x);
  else if (b < 11904) split_body(inf, ifh, ifl, (b-6464)*256 + threadIdx.x);
  else                split_body(vw, vwh, vwl, (b-11904)*256 + threadIdx.x);
}

__global__ void __launch_bounds__(256)
split_w(const float4* __restrict__ w, __nv_bfloat162* __restrict__ h,
        __nv_bfloat162* __restrict__ l) {
  split_body(w, h, l, blockIdx.x*256 + threadIdx.x);
}

// ===========================================================================
// 3-term split-bf16 GEMM body (value / out projections — precision path).
// ===========================================================================
template<int MODE, int NT>
__device__ __forceinline__ void gemm_body(
    const uint4* __restrict__ Ah, const uint4* __restrict__ Al,
    const uint4* __restrict__ Bh, const uint4* __restrict__ Bl,
    const float* __restrict__ c0,
    void* __restrict__ OutV, int r0, int N0) {
  extern __shared__ char dsm[];
  const uint32_t as = s2u(dsm);            // A: 128 rows x 1024B = 131072
  const uint32_t bsb = as + 131072u;       // B: 3 x 32768 (hi 16KB | lo 16KB)
  const int tid = threadIdx.x;
  const int wid = tid >> 5, lane = tid & 31;
  const int mw = wid & 3, nw = wid >> 2;

#pragma unroll
  for (int it = 0; it < 16; ++it) {
    int i = it*512 + tid;
    int r = i >> 6, u = i & 63;
    int half = u >> 5, uu = u & 31;
    int s = (half << 2) + (uu >> 3), c = uu & 7;
    const uint4* src = (half ? Al : Ah) + (size_t)(r0 + r)*32 + uu;
    uint32_t dst = as + (uint32_t)r*1024u + (uint32_t)s*128u + (uint32_t)((c ^ (r & 7))*16);
    CP_ASYNC16(dst, src);
  }
  CP_COMMIT();

  const int lA = mw*32 + (lane & 15);
  const int jj = lane >> 4;
  const int nB = nw*32 + (lane & 15);
  const uint32_t pA = as + (uint32_t)lA*1024u;
  const int swA = lA & 7, swB = nB & 7;

  for (int nt = 0; nt < NT; ++nt) {
    float acc[2][4][4];
#pragma unroll
    for (int a = 0; a < 2; ++a)
#pragma unroll
      for (int b = 0; b < 4; ++b)
#pragma unroll
        for (int d = 0; d < 4; ++d) acc[a][b][d] = 0.f;

    const int nrow0 = N0 + nt*128;

    auto prefetchC4 = [&](int c4, int bi) {
#pragma unroll
      for (int it = 0; it < 4; ++it) {
        int i = it*512 + tid;
        int n = i >> 4, u = i & 15;
        int sub = u >> 3, c = u & 7;
        const uint4* src = (sub ? Bl : Bh) + (size_t)(nrow0 + n)*32 + c4*8 + c;
        uint32_t dst = bsb + (uint32_t)bi*32768u + (uint32_t)sub*16384u
                     + (uint32_t)n*128u + (uint32_t)((c ^ (n & 7))*16);
        CP_ASYNC16(dst, src);
      }
      CP_COMMIT();
    };

    prefetchC4(0, 0);
    prefetchC4(1, 1);

#pragma unroll
    for (int c4 = 0; c4 < 4; ++c4) {
      if (c4 == 3) { CP_WAIT(0); } else { CP_WAIT(1); }
      __syncthreads();
      if (c4 + 2 < 4) prefetchC4(c4 + 2, (c4 + 2) % 3);

      const uint32_t bs  = bsb + (uint32_t)(c4 % 3)*32768u;
      const uint32_t aBh = pA + (uint32_t)c4*128u;
      const uint32_t aBl = pA + (uint32_t)(4 + c4)*128u;
#pragma unroll
      for (int ks = 0; ks < 4; ++ks) {
        const int cc = ks*2 + jj;
        const uint32_t csw = (uint32_t)((cc ^ swA)*16);
        uint32_t ah[2][4], al[2][4];
        ldsm4(ah[0][0], ah[0][1], ah[0][2], ah[0][3], aBh + csw);
        ldsm4(ah[1][0], ah[1][1], ah[1][2], ah[1][3], aBh + 16384u + csw);
        ldsm4(al[0][0], al[0][1], al[0][2], al[0][3], aBl + csw);
        ldsm4(al[1][0], al[1][1], al[1][2], al[1][3], aBl + 16384u + csw);
        const uint32_t bsw = (uint32_t)((cc ^ swB)*16);
        uint32_t bh[2][4], bl[2][4];
#pragma unroll
        for (int qt = 0; qt < 2; ++qt) {
          ldsm4(bh[qt][0], bh[qt][1], bh[qt][2], bh[qt][3],
                bs + (uint32_t)nB*128u + (uint32_t)qt*2048u + bsw);
          ldsm4(bl[qt][0], bl[qt][1], bl[qt][2], bl[qt][3],
                bs + 16384u + (uint32_t)nB*128u + (uint32_t)qt*2048u + bsw);
        }
#pragma unroll
        for (int qt = 0; qt < 2; ++qt)
#pragma unroll
          for (int mt = 0; mt < 2; ++mt) {
            mma16816(acc[mt][qt*2  ][0], acc[mt][qt*2  ][1], acc[mt][qt*2  ][2], acc[mt][qt*2  ][3],
                     ah[mt][0], ah[mt][1], ah[mt][2], ah[mt][3], bh[qt][0], bh[qt][2]);
            mma16816(acc[mt][qt*2+1][0], acc[mt][qt*2+1][1], acc[mt][qt*2+1][2], acc[mt][qt*2+1][3],
                     ah[mt][0], ah[mt][1], ah[mt][2], ah[mt][3], bh[qt][1], bh[qt][3]);
          }
#pragma unroll
        for (int qt = 0; qt < 2; ++qt)
#pragma unroll
          for (int mt = 0; mt < 2; ++mt) {
            mma16816(acc[mt][qt*2  ][0], acc[mt][qt*2  ][1], acc[mt][qt*2  ][2], acc[mt][qt*2  ][3],
                     al[mt][0], al[mt][1], al[mt][2], al[mt][3], bh[qt][0], bh[qt][2]);
            mma16816(acc[mt][qt*2+1][0], acc[mt][qt*2+1][1], acc[mt][qt*2+1][2], acc[mt][qt*2+1][3],
                     al[mt][0], al[mt][1], al[mt][2], al[mt][3], bh[qt][1], bh[qt][3]);
          }
#pragma unroll
        for (int qt = 0; qt < 2; ++qt)
#pragma unroll
          for (int mt = 0; mt < 2; ++mt) {
            mma16816(acc[mt][qt*2  ][0], acc[mt][qt*2  ][1], acc[mt][qt*2  ][2], acc[mt][qt*2  ][3],
                     ah[mt][0], ah[mt][1], ah[mt][2], ah[mt][3], bl[qt][0], bl[qt][2]);
            mma16816(acc[mt][qt*2+1][0], acc[mt][qt*2+1][1], acc[mt][qt*2+1][2], acc[mt][qt*2+1][3],
                     ah[mt][0], ah[mt][1], ah[mt][2], ah[mt][3], bl[qt][1], bl[qt][3]);
          }
      }
    }
    __syncthreads();

#pragma unroll
    for (int mt = 0; mt < 2; ++mt)
#pragma unroll
      for (int h = 0; h < 2; ++h) {
        int row = r0 + mw*32 + mt*16 + (lane >> 2) + h*8;
#pragma unroll
        for (int j = 0; j < 4; ++j) {
          // N0 included: block may cover a nonzero column offset (grid.y>1)
          int col = N0 + nt*128 + nw*32 + j*8 + (lane & 3)*2;
          float ox = acc[mt][j][h*2+0] + c0[col];
          float oy = acc[mt][j][h*2+1] + c0[col+1];
          if (MODE == 0) {
            float2 o; o.x = ox; o.y = oy;
            *reinterpret_cast<float2*>((float*)OutV + (size_t)row*256 + col) = o;
          } else {
            __half2 o = __floats2half2_rn(ox, oy);
            *reinterpret_cast<__half2*>((__half*)OutV + (size_t)row*256 + col) = o;
          }
        }
      }
  }
}

// ===========================================================================
// Single-pass bf16 GEMM body (offset path — error-tolerant).
// ===========================================================================
__device__ __forceinline__ void gemm1_body(
    const uint4* __restrict__ Ah, const uint4* __restrict__ Bh,
    const float* __restrict__ sow, const float* __restrict__ attw,
    float* __restrict__ Out, int r0, int N0) {
  extern __shared__ char dsm[];
  const uint32_t as = s2u(dsm);            // A: 128 rows x 512B = 65536
  const uint32_t bsb = as + 65536u;        // B: 3 x 16384
  const int tid = threadIdx.x;
  const int wid = tid >> 5, lane = tid & 31;
  const int mw = wid & 3, nw = wid >> 2;

#pragma unroll
  for (int it = 0; it < 8; ++it) {
    int i = it*512 + tid;
    int r = i >> 5, uu = i & 31;
    int s = uu >> 3, c = uu & 7;
    const uint4* src = Ah + (size_t)(r0 + r)*32 + uu;
    uint32_t dst = as + (uint32_t)r*512u + (uint32_t)s*128u + (uint32_t)((c ^ (r & 7))*16);
    CP_ASYNC16(dst, src);
  }
  CP_COMMIT();

  const int lA = mw*32 + (lane & 15);
  const int jj = lane >> 4;
  const int nB = nw*32 + (lane & 15);
  const uint32_t pA = as + (uint32_t)lA*512u;
  const int swA = lA & 7, swB = nB & 7;

  for (int nt = 0; nt < 2; ++nt) {
    float acc[2][4][4];
#pragma unroll
    for (int a = 0; a < 2; ++a)
#pragma unroll
      for (int b = 0; b < 4; ++b)
#pragma unroll
        for (int d = 0; d < 4; ++d) acc[a][b][d] = 0.f;

    const int nrow0 = N0 + nt*128;

    auto prefetchC4 = [&](int c4, int bi) {
#pragma unroll
      for (int it = 0; it < 2; ++it) {
        int i = it*512 + tid;
        int n = i >> 3, c = i & 7;
        const uint4* src = Bh + (size_t)(nrow0 + n)*32 + c4*8 + c;
        uint32_t dst = bsb + (uint32_t)bi*16384u
                     + (uint32_t)n*128u + (uint32_t)((c ^ (n & 7))*16);
        CP_ASYNC16(dst, src);
      }
      CP_COMMIT();
    };

    prefetchC4(0, 0);
    prefetchC4(1, 1);

#pragma unroll
    for (int c4 = 0; c4 < 4; ++c4) {
      if (c4 == 3) { CP_WAIT(0); } else { CP_WAIT(1); }
      __syncthreads();
      if (c4 + 2 < 4) prefetchC4(c4 + 2, (c4 + 2) % 3);

      const uint32_t bs = bsb + (uint32_t)(c4 % 3)*16384u;
      const uint32_t aB = pA + (uint32_t)c4*128u;
#pragma unroll
      for (int ks = 0; ks < 4; ++ks) {
        const int cc = ks*2 + jj;
        const uint32_t csw = (uint32_t)((cc ^ swA)*16);
        uint32_t ah[2][4];
        ldsm4(ah[0][0], ah[0][1], ah[0][2], ah[0][3], aB + csw);
        ldsm4(ah[1][0], ah[1][1], ah[1][2], ah[1][3], aB + 8192u + csw);
        const uint32_t bsw = (uint32_t)((cc ^ swB)*16);
        uint32_t bh[2][4];
#pragma unroll
        for (int qt = 0; qt < 2; ++qt)
          ldsm4(bh[qt][0], bh[qt][1], bh[qt][2], bh[qt][3],
                bs + (uint32_t)nB*128u + (uint32_t)qt*2048u + bsw);
#pragma unroll
        for (int qt = 0; qt < 2; ++qt)
#pragma unroll
          for (int mt = 0; mt < 2; ++mt) {
            mma16816(acc[mt][qt*2  ][0], acc[mt][qt*2  ][1], acc[mt][qt*2  ][2], acc[mt][qt*2  ][3],
                     ah[mt][0], ah[mt][1], ah[mt][2], ah[mt][3], bh[qt][0], bh[qt][2]);
            mma16816(acc[mt][qt*2+1][0], acc[mt][qt*2+1][1], acc[mt][qt*2+1][2], acc[mt][qt*2+1][3],
                     ah[mt][0], ah[mt][1], ah[mt][2], ah[mt][3], bh[qt][1], bh[qt][3]);
          }
      }
    }
    __syncthreads();

    const float2* sw2 = reinterpret_cast<const float2*>(sow);
    int g = (N0 + nt*128 + nw*32) >> 5;
    float wx[4][2], wy[4][2], wl[4][2];
#pragma unroll
    for (int j = 0; j < 4; ++j) {
      int col = g*32 + j*8 + (lane & 3)*2;
      float2 q0 = __ldg(&sw2[col]), q1 = __ldg(&sw2[col+1]);
      wx[j][0] = q0.x; wy[j][0] = q0.y;
      wx[j][1] = q1.x; wy[j][1] = q1.y;
      wl[j][0] = __ldg(&attw[col]); wl[j][1] = __ldg(&attw[col+1]);
    }
#pragma unroll
    for (int mt = 0; mt < 2; ++mt)
#pragma unroll
      for (int h = 0; h < 2; ++h) {
        int row = r0 + mw*32 + mt*16 + (lane >> 2) + h*8;
        float sx = 0.f, sy = 0.f, sl = 0.f;
#pragma unroll
        for (int j = 0; j < 4; ++j) {
          float v0 = silu_t(acc[mt][j][h*2+0]);
          float v1 = silu_t(acc[mt][j][h*2+1]);
          sx = fmaf(v0, wx[j][0], sx); sx = fmaf(v1, wx[j][1], sx);
          sy = fmaf(v0, wy[j][0], sy); sy = fmaf(v1, wy[j][1], sy);
          sl = fmaf(v0, wl[j][0], sl); sl = fmaf(v1, wl[j][1], sl);
        }
        sx += __shfl_xor_sync(0xffffffffu, sx, 1);
        sy += __shfl_xor_sync(0xffffffffu, sy, 1);
        sl += __shfl_xor_sync(0xffffffffu, sl, 1);
        sx += __shfl_xor_sync(0xffffffffu, sx, 2);
        sy += __shfl_xor_sync(0xffffffffu, sy, 2);
        sl += __shfl_xor_sync(0xffffffffu, sl, 2);
        if ((lane & 3) == 0) {
          float* o = Out + ((size_t)g*MTOT + row)*3;
          o[0] = sx; o[1] = sy; o[2] = sl;
        }
      }
  }
}

// mega: y==0 -> value proj (slow 3-term, scheduled FIRST); y=1..16 -> offset
__global__ void __launch_bounds__(512, 1)
mega_gemm(const uint4* __restrict__ Qh,
          const uint4* __restrict__ Wh,
          const float* __restrict__ sow, const float* __restrict__ attw,
          float* __restrict__ pofa,
          const uint4* __restrict__ Ih, const uint4* __restrict__ Il,
          const uint4* __restrict__ Vh, const uint4* __restrict__ Vl,
          const float* __restrict__ vbias, __half* __restrict__ pval) {
  const int r0 = blockIdx.x * 128;
  if (blockIdx.y == 0)
    gemm_body<2,2>(Ih, Il, Vh, Vl, vbias, pval, r0, 0);
  else
    gemm1_body(Qh, Wh, sow, attw, pofa, r0, (blockIdx.y-1)*256);
}

template<int MODE, int NT>
__global__ void __launch_bounds__(512, 1)
gemm_mma(const uint4* __restrict__ Ah, const uint4* __restrict__ Al,
         const uint4* __restrict__ Bh, const uint4* __restrict__ Bl,
         const float* __restrict__ c0, void* __restrict__ OutV) {
  gemm_body<MODE,NT>(Ah, Al, Bh, Bl, c0, OutV, blockIdx.x*128, blockIdx.y*NT*128);
}

// ===========================================================================
// Sampling: one warp per (b,q,head); 2 points per warp via half2 lanes.
// ===========================================================================
__global__ void __launch_bounds__(256)
sample_kernel(const float* __restrict__ ref, const float* __restrict__ sob,
              const float* __restrict__ attb) {
  __shared__ float s_lx[NH][16], s_ly[NH][16], s_aw[NH][16];
  const int bq   = blockIdx.x;
  const int b    = bq / LEN;
  const int h    = threadIdx.x >> 5;
  const int lane = threadIdx.x & 31;
  const int p    = lane & 15;
  const int l    = p >> 2;

  const float SZ[4] = {64.f, 32.f, 16.f, 8.f};
  int g = h*16 + p;
  size_t ob = ((size_t)g*MTOT + bq)*3;
  float rx = g_offaw[ob+0], ry = g_offaw[ob+1], rl = g_offaw[ob+2];
  float inv = 1.f / SZ[l];
  float lx = ref[(size_t)bq*8 + l*2 + 0] + (rx + sob[g*2+0]) * inv;
  float ly = ref[(size_t)bq*8 + l*2 + 1] + (ry + sob[g*2+1]) * inv;
  float logit = rl + attb[g];

  float mx = logit;
#pragma unroll
  for (int off = 8; off; off >>= 1)
    mx = fmaxf(mx, __shfl_xor_sync(0xffffffffu, mx, off, 16));
  float e = __expf(logit - mx);
  float ssum = e;
#pragma unroll
  for (int off = 8; off; off >>= 1)
    ssum += __shfl_xor_sync(0xffffffffu, ssum, off, 16);
  float aw = e / ssum;

  if (lane < 16) { s_lx[h][p] = lx; s_ly[h][p] = ly; s_aw[h][p] = aw; }
  __syncwarp(0xffffffffu);

  const int ST[4]  = {0, 4096, 5120, 5376};
  const int SZI[4] = {64, 32, 16, 8};
  const int halfid = lane >> 4;
  const int dpair  = lane & 15;
  float ax = 0.f, ay = 0.f;
  const __half2* vb2 = reinterpret_cast<const __half2*>(g_value)
                     + (size_t)b*LEN*128 + h*16 + dpair;

#pragma unroll
  for (int t = 0; t < 8; ++t) {
    int pp = t*2 + halfid;
    int ll = pp >> 2;
    int S  = SZI[ll];
    float x = s_lx[h][pp]*(float)S - 0.5f;
    float y = s_ly[h][pp]*(float)S - 0.5f;
    float w = s_aw[h][pp];
    float fx = floorf(x), fy = floorf(y);
    int x0 = (int)fx, y0 = (int)fy;
    float wx = x - fx, wy = y - fy;
    const __half2* vl = vb2 + (size_t)ST[ll]*128;
    __half2 z = __floats2half2_rn(0.f, 0.f);
    __half2 v00 = z, v01 = z, v10 = z, v11 = z;
    bool xa = (x0   >= 0) && (x0   < S);
    bool xb = (x0+1 >= 0) && (x0+1 < S);
    bool ya = (y0   >= 0) && (y0   < S);
    bool yb = (y0+1 >= 0) && (y0+1 < S);
    if (xa && ya) v00 = vl[(size_t)(y0*S + x0  )*128];
    if (xb && ya) v01 = vl[(size_t)(y0*S + x0+1)*128];
    if (xa && yb) v10 = vl[(size_t)((y0+1)*S + x0  )*128];
    if (xb && yb) v11 = vl[(size_t)((y0+1)*S + x0+1)*128];
    float2 f00 = __half22float2(v00), f01 = __half22float2(v01);
    float2 f10 = __half22float2(v10), f11 = __half22float2(v11);
    float w00 = (1.f-wx)*(1.f-wy)*w, w01 = wx*(1.f-wy)*w;
    float w10 = (1.f-wx)*wy*w,       w11 = wx*wy*w;
    ax += f00.x*w00 + f01.x*w01 + f10.x*w10 + f11.x*w11;
    ay += f00.y*w00 + f01.y*w01 + f10.y*w10 + f11.y*w11;
  }
  ax += __shfl_xor_sync(0xffffffffu, ax, 16);
  ay += __shfl_xor_sync(0xffffffffu, ay, 16);

  if (lane < 16) {
    __nv_bfloat16 hx = __float2bfloat16_rn(ax);
    __nv_bfloat16 hy = __float2bfloat16_rn(ay);
    __nv_bfloat162 hi2(hx, hy);
    __nv_bfloat162 lo2(__float2bfloat16_rn(ax - __bfloat162float(hx)),
                       __float2bfloat16_rn(ay - __bfloat162float(hy)));
    size_t idx = (size_t)bq*128 + h*16 + dpair;
    reinterpret_cast<__nv_bfloat162*>(g_mh)[idx] = hi2;
    reinterpret_cast<__nv_bfloat162*>(g_ml)[idx] = lo2;
  }
}

// ===========================================================================
extern "C" void kernel_launch(void* const* d_in, const int* in_sizes, int n_in,
                              void* d_out, int out_size) {
  (void)in_sizes; (void)n_in; (void)out_size;
  const float* query  = (const float*)d_in[0];
  const float* ref    = (const float*)d_in[1];
  const float* inputf = (const float*)d_in[2];
  const float* oeW    = (const float*)d_in[4];
  const float* sow    = (const float*)d_in[5];
  const float* sob    = (const float*)d_in[6];
  const float* attW   = (const float*)d_in[7];
  const float* attb   = (const float*)d_in[8];
  const float* valW   = (const float*)d_in[9];
  const float* valb   = (const float*)d_in[10];
  const float* outW   = (const float*)d_in[11];
  const float* outb   = (const float*)d_in[12];
  float* out = (float*)d_out;

  uint4 *qh,*ifh,*ifl,*mh,*ml,*wembh,*vwh,*vwl,*owh,*owl;
  void *pval; float *pofa;
  cudaGetSymbolAddress((void**)&qh, g_qh);
  cudaGetSymbolAddress((void**)&ifh, g_ifh);   cudaGetSymbolAddress((void**)&ifl, g_ifl);
  cudaGetSymbolAddress((void**)&mh, g_mh);     cudaGetSymbolAddress((void**)&ml, g_ml);
  cudaGetSymbolAddress((void**)&wembh, g_wembh);
  cudaGetSymbolAddress((void**)&vwh, g_vwh);   cudaGetSymbolAddress((void**)&vwl, g_vwl);
  cudaGetSymbolAddress((void**)&owh, g_owh);   cudaGetSymbolAddress((void**)&owl, g_owl);
  cudaGetSymbolAddress((void**)&pval, g_value);
  cudaGetSymbolAddress((void**)&pofa, g_offaw);

  const int dynsmem = 131072 + 3*32768;  // 224 KB (covers both bodies)
  cudaFuncSetAttribute(mega_gemm, cudaFuncAttributeMaxDynamicSharedMemorySize, dynsmem);
  cudaFuncSetAttribute(gemm_mma<0,1>, cudaFuncAttributeMaxDynamicSharedMemorySize, dynsmem);

  split_all<<<11968, 256>>>(reinterpret_cast<const float4*>(query),
                            reinterpret_cast<__nv_bfloat162*>(qh),
                            reinterpret_cast<const float4*>(oeW),
                            reinterpret_cast<__nv_bfloat162*>(wembh),
                            reinterpret_cast<const float4*>(inputf),
                            reinterpret_cast<__nv_bfloat162*>(ifh),
                            reinterpret_cast<__nv_bfloat162*>(ifl),
                            reinterpret_cast<const float4*>(valW),
                            reinterpret_cast<__nv_bfloat162*>(vwh),
                            reinterpret_cast<__nv_bfloat162*>(vwl));          // 0
  mega_gemm<<<dim3(MTOT/128,17), 512, dynsmem>>>(qh, wembh, sow, attW, pofa,
                                                 ifh, ifl, vwh, vwl,
                                                 valb, (__half*)pval);        // 1
  split_w<<<64, 256>>>(reinterpret_cast<const float4*>(outW),
                       reinterpret_cast<__nv_bfloat162*>(owh),
                       reinterpret_cast<__nv_bfloat162*>(owl));               // 2
  sample_kernel<<<MTOT, 256>>>(ref, sob, attb);                               // 3 (ncu)
  gemm_mma<0,1><<<dim3(MTOT/128,2), 512, dynsmem>>>(mh, ml, owh, owl,
                                                    outb, out);               // 4
}

// round 17
// speedup vs baseline: 1.9525x; 1.0658x over previous
#include <cuda_runtime.h>
#include <cuda_bf16.h>
#include <cuda_fp16.h>
#include <math.h>
#include <stdint.h>

#define NB   4
#define LEN  5440
#define MTOT (NB*LEN)      // 21760
#define DM   256
#define NH   8
#define NG   128

// ===========================================================================
// Scratch (allocation-free __device__ globals)
// ===========================================================================
__device__ uint4 g_qh[MTOT*32];                      // query bf16 hi (row-major)
__device__ uint4 g_ifh[MTOT*32], g_ifl[MTOT*32];     // input_flatten split
__device__ uint4 g_mh[MTOT*32],  g_ml[MTOT*32];      // mix (sample output) split
__device__ uint4 g_wembh[4096*32];                   // offset-embed W bf16 hi
__device__ uint4 g_vwh[256*32],   g_vwl[256*32];     // value W split
__device__ uint4 g_owh[256*32],   g_owl[256*32];     // out W split
__device__ __half g_value[MTOT*DM];                  // value projection (fp16)
__device__ float g_offaw[(size_t)NG*MTOT*3];         // [group][row][3]

// ===========================================================================
__device__ __forceinline__ uint32_t s2u(const void* p) {
  uint32_t a;
  asm("{ .reg .u64 t; cvta.to.shared.u64 t, %1; cvt.u32.u64 %0, t; }" : "=r"(a) : "l"(p));
  return a;
}
__device__ __forceinline__ void ldsm4(uint32_t& r0, uint32_t& r1, uint32_t& r2,
                                      uint32_t& r3, uint32_t addr) {
  asm volatile("ldmatrix.sync.aligned.m8n8.x4.shared.b16 {%0,%1,%2,%3}, [%4];"
               : "=r"(r0), "=r"(r1), "=r"(r2), "=r"(r3) : "r"(addr));
}
__device__ __forceinline__ void mma16816(float& c0, float& c1, float& c2, float& c3,
                                         uint32_t a0, uint32_t a1, uint32_t a2, uint32_t a3,
                                         uint32_t b0, uint32_t b1) {
  asm volatile("mma.sync.aligned.m16n8k16.row.col.f32.bf16.bf16.f32 "
               "{%0,%1,%2,%3}, {%4,%5,%6,%7}, {%8,%9}, {%0,%1,%2,%3};"
               : "+f"(c0), "+f"(c1), "+f"(c2), "+f"(c3)
               : "r"(a0), "r"(a1), "r"(a2), "r"(a3), "r"(b0), "r"(b1));
}
// silu via tanh.approx: v*sigmoid(v) = 0.5*v*(1+tanh(v/2)). 1 MUFU + mul + fma.
__device__ __forceinline__ float silu_t(float v) {
  float t;
  asm("tanh.approx.f32 %0, %1;" : "=f"(t) : "f"(v*0.5f));
  return fmaf(0.5f*v, t, 0.5f*v);
}
#define CP_ASYNC16(dst, src) \
  asm volatile("cp.async.cg.shared.global [%0], [%1], 16;" :: "r"(dst), "l"(src))
#define CP_COMMIT() asm volatile("cp.async.commit_group;")
#define CP_WAIT(n)  asm volatile("cp.async.wait_group %0;" :: "n"(n) : "memory")

// ===========================================================================
// prep kernels
// ===========================================================================
__device__ __forceinline__ void split_body(const float4* __restrict__ in,
                                           __nv_bfloat162* __restrict__ hi,
                                           __nv_bfloat162* __restrict__ lo, int i) {
  float4 v = in[i];
  __nv_bfloat16 hx = __float2bfloat16_rn(v.x);
  __nv_bfloat16 hy = __float2bfloat16_rn(v.y);
  __nv_bfloat16 hz = __float2bfloat16_rn(v.z);
  __nv_bfloat16 hw = __float2bfloat16_rn(v.w);
  hi[2*i+0] = __nv_bfloat162(hx, hy);
  hi[2*i+1] = __nv_bfloat162(hz, hw);
  lo[2*i+0] = __nv_bfloat162(__float2bfloat16_rn(v.x - __bfloat162float(hx)),
                             __float2bfloat16_rn(v.y - __bfloat162float(hy)));
  lo[2*i+1] = __nv_bfloat162(__float2bfloat16_rn(v.z - __bfloat162float(hz)),
                             __float2bfloat16_rn(v.w - __bfloat162float(hw)));
}

__device__ __forceinline__ void hi_body(const float4* __restrict__ in,
                                        __nv_bfloat162* __restrict__ hi, int i) {
  float4 v = in[i];
  hi[2*i+0] = __nv_bfloat162(__float2bfloat16_rn(v.x), __float2bfloat16_rn(v.y));
  hi[2*i+1] = __nv_bfloat162(__float2bfloat16_rn(v.z), __float2bfloat16_rn(v.w));
}

// one launch: query hi (0..5439), oeW hi (5440..6463), input_flatten split
// (6464..11903), valW split (11904..11967)
__global__ void __launch_bounds__(256)
split_all(const float4* __restrict__ q,   __nv_bfloat162* __restrict__ qh,
          const float4* __restrict__ oew, __nv_bfloat162* __restrict__ wembh,
          const float4* __restrict__ inf, __nv_bfloat162* __restrict__ ifh,
          __nv_bfloat162* __restrict__ ifl,
          const float4* __restrict__ vw,  __nv_bfloat162* __restrict__ vwh,
          __nv_bfloat162* __restrict__ vwl) {
  int b = blockIdx.x;
  if (b < 5440)       hi_body(q, qh, b*256 + threadIdx.x);
  else if (b < 6464)  hi_body(oew, wembh, (b-5440)*256 + threadIdx.x);
  else if (b < 11904) split_body(inf, ifh, ifl, (b-6464)*256 + threadIdx.x);
  else                split_body(vw, vwh, vwl, (b-11904)*256 + threadIdx.x);
}

__global__ void __launch_bounds__(256)
split_w(const float4* __restrict__ w, __nv_bfloat162* __restrict__ h,
        __nv_bfloat162* __restrict__ l) {
  split_body(w, h, l, blockIdx.x*256 + threadIdx.x);
}

// ===========================================================================
// 3-term split-bf16 GEMM body (value / out projections — precision path).
// ===========================================================================
template<int MODE, int NT>
__device__ __forceinline__ void gemm_body(
    const uint4* __restrict__ Ah, const uint4* __restrict__ Al,
    const uint4* __restrict__ Bh, const uint4* __restrict__ Bl,
    const float* __restrict__ c0,
    void* __restrict__ OutV, int r0, int N0) {
  extern __shared__ char dsm[];
  const uint32_t as = s2u(dsm);            // A: 128 rows x 1024B = 131072
  const uint32_t bsb = as + 131072u;       // B: 3 x 32768 (hi 16KB | lo 16KB)
  const int tid = threadIdx.x;
  const int wid = tid >> 5, lane = tid & 31;
  const int mw = wid & 3, nw = wid >> 2;

#pragma unroll
  for (int it = 0; it < 16; ++it) {
    int i = it*512 + tid;
    int r = i >> 6, u = i & 63;
    int half = u >> 5, uu = u & 31;
    int s = (half << 2) + (uu >> 3), c = uu & 7;
    const uint4* src = (half ? Al : Ah) + (size_t)(r0 + r)*32 + uu;
    uint32_t dst = as + (uint32_t)r*1024u + (uint32_t)s*128u + (uint32_t)((c ^ (r & 7))*16);
    CP_ASYNC16(dst, src);
  }
  CP_COMMIT();

  const int lA = mw*32 + (lane & 15);
  const int jj = lane >> 4;
  const int nB = nw*32 + (lane & 15);
  const uint32_t pA = as + (uint32_t)lA*1024u;
  const int swA = lA & 7, swB = nB & 7;

  for (int nt = 0; nt < NT; ++nt) {
    float acc[2][4][4];
#pragma unroll
    for (int a = 0; a < 2; ++a)
#pragma unroll
      for (int b = 0; b < 4; ++b)
#pragma unroll
        for (int d = 0; d < 4; ++d) acc[a][b][d] = 0.f;

    const int nrow0 = N0 + nt*128;

    auto prefetchC4 = [&](int c4, int bi) {
#pragma unroll
      for (int it = 0; it < 4; ++it) {
        int i = it*512 + tid;
        int n = i >> 4, u = i & 15;
        int sub = u >> 3, c = u & 7;
        const uint4* src = (sub ? Bl : Bh) + (size_t)(nrow0 + n)*32 + c4*8 + c;
        uint32_t dst = bsb + (uint32_t)bi*32768u + (uint32_t)sub*16384u
                     + (uint32_t)n*128u + (uint32_t)((c ^ (n & 7))*16);
        CP_ASYNC16(dst, src);
      }
      CP_COMMIT();
    };

    prefetchC4(0, 0);
    prefetchC4(1, 1);

#pragma unroll
    for (int c4 = 0; c4 < 4; ++c4) {
      if (c4 == 3) { CP_WAIT(0); } else { CP_WAIT(1); }
      __syncthreads();
      if (c4 + 2 < 4) prefetchC4(c4 + 2, (c4 + 2) % 3);

      const uint32_t bs  = bsb + (uint32_t)(c4 % 3)*32768u;
      const uint32_t aBh = pA + (uint32_t)c4*128u;
      const uint32_t aBl = pA + (uint32_t)(4 + c4)*128u;
#pragma unroll
      for (int ks = 0; ks < 4; ++ks) {
        const int cc = ks*2 + jj;
        const uint32_t csw = (uint32_t)((cc ^ swA)*16);
        uint32_t ah[2][4], al[2][4];
        ldsm4(ah[0][0], ah[0][1], ah[0][2], ah[0][3], aBh + csw);
        ldsm4(ah[1][0], ah[1][1], ah[1][2], ah[1][3], aBh + 16384u + csw);
        ldsm4(al[0][0], al[0][1], al[0][2], al[0][3], aBl + csw);
        ldsm4(al[1][0], al[1][1], al[1][2], al[1][3], aBl + 16384u + csw);
        const uint32_t bsw = (uint32_t)((cc ^ swB)*16);
        uint32_t bh[2][4], bl[2][4];
#pragma unroll
        for (int qt = 0; qt < 2; ++qt) {
          ldsm4(bh[qt][0], bh[qt][1], bh[qt][2], bh[qt][3],
                bs + (uint32_t)nB*128u + (uint32_t)qt*2048u + bsw);
          ldsm4(bl[qt][0], bl[qt][1], bl[qt][2], bl[qt][3],
                bs + 16384u + (uint32_t)nB*128u + (uint32_t)qt*2048u + bsw);
        }
#pragma unroll
        for (int qt = 0; qt < 2; ++qt)
#pragma unroll
          for (int mt = 0; mt < 2; ++mt) {
            mma16816(acc[mt][qt*2  ][0], acc[mt][qt*2  ][1], acc[mt][qt*2  ][2], acc[mt][qt*2  ][3],
                     ah[mt][0], ah[mt][1], ah[mt][2], ah[mt][3], bh[qt][0], bh[qt][2]);
            mma16816(acc[mt][qt*2+1][0], acc[mt][qt*2+1][1], acc[mt][qt*2+1][2], acc[mt][qt*2+1][3],
                     ah[mt][0], ah[mt][1], ah[mt][2], ah[mt][3], bh[qt][1], bh[qt][3]);
          }
#pragma unroll
        for (int qt = 0; qt < 2; ++qt)
#pragma unroll
          for (int mt = 0; mt < 2; ++mt) {
            mma16816(acc[mt][qt*2  ][0], acc[mt][qt*2  ][1], acc[mt][qt*2  ][2], acc[mt][qt*2  ][3],
                     al[mt][0], al[mt][1], al[mt][2], al[mt][3], bh[qt][0], bh[qt][2]);
            mma16816(acc[mt][qt*2+1][0], acc[mt][qt*2+1][1], acc[mt][qt*2+1][2], acc[mt][qt*2+1][3],
                     al[mt][0], al[mt][1], al[mt][2], al[mt][3], bh[qt][1], bh[qt][3]);
          }
#pragma unroll
        for (int qt = 0; qt < 2; ++qt)
#pragma unroll
          for (int mt = 0; mt < 2; ++mt) {
            mma16816(acc[mt][qt*2  ][0], acc[mt][qt*2  ][1], acc[mt][qt*2  ][2], acc[mt][qt*2  ][3],
                     ah[mt][0], ah[mt][1], ah[mt][2], ah[mt][3], bl[qt][0], bl[qt][2]);
            mma16816(acc[mt][qt*2+1][0], acc[mt][qt*2+1][1], acc[mt][qt*2+1][2], acc[mt][qt*2+1][3],
                     ah[mt][0], ah[mt][1], ah[mt][2], ah[mt][3], bl[qt][1], bl[qt][3]);
          }
      }
    }
    __syncthreads();

#pragma unroll
    for (int mt = 0; mt < 2; ++mt)
#pragma unroll
      for (int h = 0; h < 2; ++h) {
        int row = r0 + mw*32 + mt*16 + (lane >> 2) + h*8;
#pragma unroll
        for (int j = 0; j < 4; ++j) {
          int col = N0 + nt*128 + nw*32 + j*8 + (lane & 3)*2;
          float ox = acc[mt][j][h*2+0] + c0[col];
          float oy = acc[mt][j][h*2+1] + c0[col+1];
          if (MODE == 0) {
            float2 o; o.x = ox; o.y = oy;
            *reinterpret_cast<float2*>((float*)OutV + (size_t)row*256 + col) = o;
          } else {
            __half2 o = __floats2half2_rn(ox, oy);
            *reinterpret_cast<__half2*>((__half*)OutV + (size_t)row*256 + col) = o;
          }
        }
      }
  }
}

// ===========================================================================
// Single-pass bf16 GEMM body (offset path — error-tolerant).
// ===========================================================================
__device__ __forceinline__ void gemm1_body(
    const uint4* __restrict__ Ah, const uint4* __restrict__ Bh,
    const float* __restrict__ sow, const float* __restrict__ attw,
    float* __restrict__ Out, int r0, int N0) {
  extern __shared__ char dsm[];
  const uint32_t as = s2u(dsm);            // A: 128 rows x 512B = 65536
  const uint32_t bsb = as + 65536u;        // B: 3 x 16384
  const int tid = threadIdx.x;
  const int wid = tid >> 5, lane = tid & 31;
  const int mw = wid & 3, nw = wid >> 2;

#pragma unroll
  for (int it = 0; it < 8; ++it) {
    int i = it*512 + tid;
    int r = i >> 5, uu = i & 31;
    int s = uu >> 3, c = uu & 7;
    const uint4* src = Ah + (size_t)(r0 + r)*32 + uu;
    uint32_t dst = as + (uint32_t)r*512u + (uint32_t)s*128u + (uint32_t)((c ^ (r & 7))*16);
    CP_ASYNC16(dst, src);
  }
  CP_COMMIT();

  const int lA = mw*32 + (lane & 15);
  const int jj = lane >> 4;
  const int nB = nw*32 + (lane & 15);
  const uint32_t pA = as + (uint32_t)lA*512u;
  const int swA = lA & 7, swB = nB & 7;

  for (int nt = 0; nt < 2; ++nt) {
    float acc[2][4][4];
#pragma unroll
    for (int a = 0; a < 2; ++a)
#pragma unroll
      for (int b = 0; b < 4; ++b)
#pragma unroll
        for (int d = 0; d < 4; ++d) acc[a][b][d] = 0.f;

    const int nrow0 = N0 + nt*128;

    auto prefetchC4 = [&](int c4, int bi) {
#pragma unroll
      for (int it = 0; it < 2; ++it) {
        int i = it*512 + tid;
        int n = i >> 3, c = i & 7;
        const uint4* src = Bh + (size_t)(nrow0 + n)*32 + c4*8 + c;
        uint32_t dst = bsb + (uint32_t)bi*16384u
                     + (uint32_t)n*128u + (uint32_t)((c ^ (n & 7))*16);
        CP_ASYNC16(dst, src);
      }
      CP_COMMIT();
    };

    prefetchC4(0, 0);
    prefetchC4(1, 1);

#pragma unroll
    for (int c4 = 0; c4 < 4; ++c4) {
      if (c4 == 3) { CP_WAIT(0); } else { CP_WAIT(1); }
      __syncthreads();
      if (c4 + 2 < 4) prefetchC4(c4 + 2, (c4 + 2) % 3);

      const uint32_t bs = bsb + (uint32_t)(c4 % 3)*16384u;
      const uint32_t aB = pA + (uint32_t)c4*128u;
#pragma unroll
      for (int ks = 0; ks < 4; ++ks) {
        const int cc = ks*2 + jj;
        const uint32_t csw = (uint32_t)((cc ^ swA)*16);
        uint32_t ah[2][4];
        ldsm4(ah[0][0], ah[0][1], ah[0][2], ah[0][3], aB + csw);
        ldsm4(ah[1][0], ah[1][1], ah[1][2], ah[1][3], aB + 8192u + csw);
        const uint32_t bsw = (uint32_t)((cc ^ swB)*16);
        uint32_t bh[2][4];
#pragma unroll
        for (int qt = 0; qt < 2; ++qt)
          ldsm4(bh[qt][0], bh[qt][1], bh[qt][2], bh[qt][3],
                bs + (uint32_t)nB*128u + (uint32_t)qt*2048u + bsw);
#pragma unroll
        for (int qt = 0; qt < 2; ++qt)
#pragma unroll
          for (int mt = 0; mt < 2; ++mt) {
            mma16816(acc[mt][qt*2  ][0], acc[mt][qt*2  ][1], acc[mt][qt*2  ][2], acc[mt][qt*2  ][3],
                     ah[mt][0], ah[mt][1], ah[mt][2], ah[mt][3], bh[qt][0], bh[qt][2]);
            mma16816(acc[mt][qt*2+1][0], acc[mt][qt*2+1][1], acc[mt][qt*2+1][2], acc[mt][qt*2+1][3],
                     ah[mt][0], ah[mt][1], ah[mt][2], ah[mt][3], bh[qt][1], bh[qt][3]);
          }
      }
    }
    __syncthreads();

    const float2* sw2 = reinterpret_cast<const float2*>(sow);
    int g = (N0 + nt*128 + nw*32) >> 5;
    float wx[4][2], wy[4][2], wl[4][2];
#pragma unroll
    for (int j = 0; j < 4; ++j) {
      int col = g*32 + j*8 + (lane & 3)*2;
      float2 q0 = __ldg(&sw2[col]), q1 = __ldg(&sw2[col+1]);
      wx[j][0] = q0.x; wy[j][0] = q0.y;
      wx[j][1] = q1.x; wy[j][1] = q1.y;
      wl[j][0] = __ldg(&attw[col]); wl[j][1] = __ldg(&attw[col+1]);
    }
#pragma unroll
    for (int mt = 0; mt < 2; ++mt)
#pragma unroll
      for (int h = 0; h < 2; ++h) {
        int row = r0 + mw*32 + mt*16 + (lane >> 2) + h*8;
        float sx = 0.f, sy = 0.f, sl = 0.f;
#pragma unroll
        for (int j = 0; j < 4; ++j) {
          float v0 = silu_t(acc[mt][j][h*2+0]);
          float v1 = silu_t(acc[mt][j][h*2+1]);
          sx = fmaf(v0, wx[j][0], sx); sx = fmaf(v1, wx[j][1], sx);
          sy = fmaf(v0, wy[j][0], sy); sy = fmaf(v1, wy[j][1], sy);
          sl = fmaf(v0, wl[j][0], sl); sl = fmaf(v1, wl[j][1], sl);
        }
        sx += __shfl_xor_sync(0xffffffffu, sx, 1);
        sy += __shfl_xor_sync(0xffffffffu, sy, 1);
        sl += __shfl_xor_sync(0xffffffffu, sl, 1);
        sx += __shfl_xor_sync(0xffffffffu, sx, 2);
        sy += __shfl_xor_sync(0xffffffffu, sy, 2);
        sl += __shfl_xor_sync(0xffffffffu, sl, 2);
        if ((lane & 3) == 0) {
          float* o = Out + ((size_t)g*MTOT + row)*3;
          o[0] = sx; o[1] = sy; o[2] = sl;
        }
      }
  }
}

// mega: y==0 -> value proj (slow 3-term, scheduled FIRST); y=1..16 -> offset
__global__ void __launch_bounds__(512, 1)
mega_gemm(const uint4* __restrict__ Qh,
          const uint4* __restrict__ Wh,
          const float* __restrict__ sow, const float* __restrict__ attw,
          float* __restrict__ pofa,
          const uint4* __restrict__ Ih, const uint4* __restrict__ Il,
          const uint4* __restrict__ Vh, const uint4* __restrict__ Vl,
          const float* __restrict__ vbias, __half* __restrict__ pval) {
  const int r0 = blockIdx.x * 128;
  if (blockIdx.y == 0)
    gemm_body<2,2>(Ih, Il, Vh, Vl, vbias, pval, r0, 0);
  else
    gemm1_body(Qh, Wh, sow, attw, pofa, r0, (blockIdx.y-1)*256);
}

template<int MODE, int NT>
__global__ void __launch_bounds__(512, 1)
gemm_mma(const uint4* __restrict__ Ah, const uint4* __restrict__ Al,
         const uint4* __restrict__ Bh, const uint4* __restrict__ Bl,
         const float* __restrict__ c0, void* __restrict__ OutV) {
  gemm_body<MODE,NT>(Ah, Al, Bh, Bl, c0, OutV, blockIdx.x*128, blockIdx.y*NT*128);
}

// ===========================================================================
// Sampling: one warp per (b,q,head). Phase 1: lanes<16 precompute clamped
// corner offsets + validity-folded weights into smem (int4+float4 per point).
// Phase 2: branch-free gather loop (2 LDS.128 + 4 LDG + 8 FMA per point).
// ===========================================================================
__global__ void __launch_bounds__(256)
sample_kernel(const float* __restrict__ ref, const float* __restrict__ sob,
              const float* __restrict__ attb) {
  __shared__ int4   s_ad[NH][16];
  __shared__ float4 s_wt[NH][16];
  const int bq   = blockIdx.x;
  const int b    = bq / LEN;
  const int h    = threadIdx.x >> 5;
  const int lane = threadIdx.x & 31;
  const int p    = lane & 15;
  const int l    = p >> 2;

  const float SZ[4]  = {64.f, 32.f, 16.f, 8.f};
  const int   SZI[4] = {64, 32, 16, 8};
  const int   ST[4]  = {0, 4096, 5120, 5376};

  int g = h*16 + p;
  size_t ob = ((size_t)g*MTOT + bq)*3;
  float rx = g_offaw[ob+0], ry = g_offaw[ob+1], rl = g_offaw[ob+2];
  float inv = 1.f / SZ[l];
  float lx = ref[(size_t)bq*8 + l*2 + 0] + (rx + sob[g*2+0]) * inv;
  float ly = ref[(size_t)bq*8 + l*2 + 1] + (ry + sob[g*2+1]) * inv;
  float logit = rl + attb[g];

  float mx = logit;
#pragma unroll
  for (int off = 8; off; off >>= 1)
    mx = fmaxf(mx, __shfl_xor_sync(0xffffffffu, mx, off, 16));
  float e = __expf(logit - mx);
  float ssum = e;
#pragma unroll
  for (int off = 8; off; off >>= 1)
    ssum += __shfl_xor_sync(0xffffffffu, ssum, off, 16);
  float aw = e / ssum;

  if (lane < 16) {
    int S = SZI[l];
    float x = lx*(float)S - 0.5f;
    float y = ly*(float)S - 0.5f;
    float fx = floorf(x), fy = floorf(y);
    int x0 = (int)fx, y0 = (int)fy;
    float wx = x - fx, wy = y - fy;
    int x0c = min(max(x0, 0), S-1),   x1c = min(max(x0+1, 0), S-1);
    int y0c = min(max(y0, 0), S-1),   y1c = min(max(y0+1, 0), S-1);
    float vx0 = (x0 >= 0 && x0 < S) ? 1.f : 0.f;
    float vx1 = (x0+1 >= 0 && x0+1 < S) ? 1.f : 0.f;
    float vy0 = (y0 >= 0 && y0 < S) ? 1.f : 0.f;
    float vy1 = (y0+1 >= 0 && y0+1 < S) ? 1.f : 0.f;
    int base = ST[l];
    s_ad[h][p] = make_int4((base + y0c*S + x0c)*128, (base + y0c*S + x1c)*128,
                           (base + y1c*S + x0c)*128, (base + y1c*S + x1c)*128);
    s_wt[h][p] = make_float4((1.f-wx)*(1.f-wy)*aw*vx0*vy0,
                             wx*(1.f-wy)*aw*vx1*vy0,
                             (1.f-wx)*wy*aw*vx0*vy1,
                             wx*wy*aw*vx1*vy1);
  }
  __syncwarp(0xffffffffu);

  const int halfid = lane >> 4;
  const int dpair  = lane & 15;
  float ax = 0.f, ay = 0.f;
  const __half2* vb2 = reinterpret_cast<const __half2*>(g_value)
                     + (size_t)b*LEN*128 + h*16 + dpair;

#pragma unroll
  for (int t = 0; t < 8; ++t) {
    int pp = t*2 + halfid;
    int4   A = s_ad[h][pp];
    float4 W = s_wt[h][pp];
    float2 f00 = __half22float2(vb2[A.x]);
    float2 f01 = __half22float2(vb2[A.y]);
    float2 f10 = __half22float2(vb2[A.z]);
    float2 f11 = __half22float2(vb2[A.w]);
    ax = fmaf(f00.x, W.x, ax); ax = fmaf(f01.x, W.y, ax);
    ax = fmaf(f10.x, W.z, ax); ax = fmaf(f11.x, W.w, ax);
    ay = fmaf(f00.y, W.x, ay); ay = fmaf(f01.y, W.y, ay);
    ay = fmaf(f10.y, W.z, ay); ay = fmaf(f11.y, W.w, ay);
  }
  ax += __shfl_xor_sync(0xffffffffu, ax, 16);
  ay += __shfl_xor_sync(0xffffffffu, ay, 16);

  if (lane < 16) {
    __nv_bfloat16 hx = __float2bfloat16_rn(ax);
    __nv_bfloat16 hy = __float2bfloat16_rn(ay);
    __nv_bfloat162 hi2(hx, hy);
    __nv_bfloat162 lo2(__float2bfloat16_rn(ax - __bfloat162float(hx)),
                       __float2bfloat16_rn(ay - __bfloat162float(hy)));
    size_t idx = (size_t)bq*128 + h*16 + dpair;
    reinterpret_cast<__nv_bfloat162*>(g_mh)[idx] = hi2;
    reinterpret_cast<__nv_bfloat162*>(g_ml)[idx] = lo2;
  }
}

// ===========================================================================
extern "C" void kernel_launch(void* const* d_in, const int* in_sizes, int n_in,
                              void* d_out, int out_size) {
  (void)in_sizes; (void)n_in; (void)out_size;
  const float* query  = (const float*)d_in[0];
  const float* ref    = (const float*)d_in[1];
  const float* inputf = (const float*)d_in[2];
  const float* oeW    = (const float*)d_in[4];
  const float* sow    = (const float*)d_in[5];
  const float* sob    = (const float*)d_in[6];
  const float* attW   = (const float*)d_in[7];
  const float* attb   = (const float*)d_in[8];
  const float* valW   = (const float*)d_in[9];
  const float* valb   = (const float*)d_in[10];
  const float* outW   = (const float*)d_in[11];
  const float* outb   = (const float*)d_in[12];
  float* out = (float*)d_out;

  uint4 *qh,*ifh,*ifl,*mh,*ml,*wembh,*vwh,*vwl,*owh,*owl;
  void *pval; float *pofa;
  cudaGetSymbolAddress((void**)&qh, g_qh);
  cudaGetSymbolAddress((void**)&ifh, g_ifh);   cudaGetSymbolAddress((void**)&ifl, g_ifl);
  cudaGetSymbolAddress((void**)&mh, g_mh);     cudaGetSymbolAddress((void**)&ml, g_ml);
  cudaGetSymbolAddress((void**)&wembh, g_wembh);
  cudaGetSymbolAddress((void**)&vwh, g_vwh);   cudaGetSymbolAddress((void**)&vwl, g_vwl);
  cudaGetSymbolAddress((void**)&owh, g_owh);   cudaGetSymbolAddress((void**)&owl, g_owl);
  cudaGetSymbolAddress((void**)&pval, g_value);
  cudaGetSymbolAddress((void**)&pofa, g_offaw);

  const int dynsmem = 131072 + 3*32768;  // 224 KB (covers both bodies)
  cudaFuncSetAttribute(mega_gemm, cudaFuncAttributeMaxDynamicSharedMemorySize, dynsmem);
  cudaFuncSetAttribute(gemm_mma<0,1>, cudaFuncAttributeMaxDynamicSharedMemorySize, dynsmem);

  split_all<<<11968, 256>>>(reinterpret_cast<const float4*>(query),
                            reinterpret_cast<__nv_bfloat162*>(qh),
                            reinterpret_cast<const float4*>(oeW),
                            reinterpret_cast<__nv_bfloat162*>(wembh),
                            reinterpret_cast<const float4*>(inputf),
                            reinterpret_cast<__nv_bfloat162*>(ifh),
                            reinterpret_cast<__nv_bfloat162*>(ifl),
                            reinterpret_cast<const float4*>(valW),
                            reinterpret_cast<__nv_bfloat162*>(vwh),
                            reinterpret_cast<__nv_bfloat162*>(vwl));          // 0
  mega_gemm<<<dim3(MTOT/128,17), 512, dynsmem>>>(qh, wembh, sow, attW, pofa,
                                                 ifh, ifl, vwh, vwl,
                                                 valb, (__half*)pval);        // 1
  split_w<<<64, 256>>>(reinterpret_cast<const float4*>(outW),
                       reinterpret_cast<__nv_bfloat162*>(owh),
                       reinterpret_cast<__nv_bfloat162*>(owl));               // 2
  sample_kernel<<<MTOT, 256>>>(ref, sob, attb);                               // 3 (ncu)
  gemm_mma<0,1><<<dim3(MTOT/128,2), 512, dynsmem>>>(mh, ml, owh, owl,
                                                    outb, out);               // 4
}